// round 2
// baseline (speedup 1.0000x reference)
#include <cuda_runtime.h>
#include <cstdint>
#include <math.h>

#define N_NODES 100000
#define HID     128
#define NUM_CLS 20
#define N_EDGES 625000

// ---------------- scratch (static device globals; no allocation) ----------------
__device__ float d_summed[N_NODES * HID];   // 51.2 MB
__device__ int   d_counts[N_NODES];
__device__ float d_h[N_NODES * HID];        // 51.2 MB
__device__ float d_Wn[HID * NUM_CLS];       // col-normalized classifier weight

// ---------------- kernel 1: zero scratch ----------------
__global__ void zero_kernel() {
    int idx = blockIdx.x * blockDim.x + threadIdx.x;
    int stride = gridDim.x * blockDim.x;
    float4* s4 = reinterpret_cast<float4*>(d_summed);
    const int n4 = N_NODES * HID / 4;
    for (int i = idx; i < n4; i += stride) s4[i] = make_float4(0.f, 0.f, 0.f, 0.f);
    for (int i = idx; i < N_NODES; i += stride) d_counts[i] = 0;
}

// ---------------- kernel 2: column-normalize W_cls (tiny) ----------------
__global__ void normw_kernel(const float* __restrict__ Wc) {
    int c = threadIdx.x;
    if (c >= NUM_CLS) return;
    float s = 0.f;
    for (int j = 0; j < HID; j++) {
        float v = Wc[j * NUM_CLS + c];
        s += v * v;
    }
    float inv = 1.f / fmaxf(sqrtf(s), 1e-12f);
    for (int j = 0; j < HID; j++)
        d_Wn[j * NUM_CLS + c] = Wc[j * NUM_CLS + c] * inv;
}

// ---------------- kernel 3: edge scatter (warp per edge) ----------------
// NOTE: edge_index arrives as int32 (JAX default config demotes int64 -> int32).
__global__ void scatter_kernel(const float* __restrict__ x,
                               const int* __restrict__ ei) {
    int gw   = (blockIdx.x * blockDim.x + threadIdx.x) >> 5;
    int lane = threadIdx.x & 31;
    if (gw >= N_EDGES) return;
    int src = __ldg(&ei[gw]);            // row 0 of edge_index
    int dst = __ldg(&ei[N_EDGES + gw]);  // row 1
    const float4* xp = reinterpret_cast<const float4*>(x + (size_t)src * HID);
    float4 v = __ldg(xp + lane);               // 16B per lane = 128 floats per warp
    float* p = d_summed + (size_t)dst * HID + lane * 4;
    asm volatile("red.global.add.v4.f32 [%0], {%1,%2,%3,%4};"
                 :: "l"(p), "f"(v.x), "f"(v.y), "f"(v.z), "f"(v.w)
                 : "memory");
    if (lane == 0) atomicAdd(&d_counts[dst], 1);
}

// ---------------- kernel 4: fused GEMM  h = [aggr|x] @ [W_l;W_r] + b ----------------
// Block tile 128 rows x 128 cols, K=256. Full weight resident in shared (128 KB).
// 256 threads, 8x8 micro-tiles.
#define SMEM_FLOATS (32768 + 16 * 132 + 128 + 128)

__global__ __launch_bounds__(256, 1)
void gemm_kernel(const float* __restrict__ x,
                 const float* __restrict__ Wl,
                 const float* __restrict__ bl,
                 const float* __restrict__ Wr) {
    extern __shared__ float smem[];
    float* Ws   = smem;                 // [256][128]  combined [W_l; W_r]
    float* As   = smem + 32768;         // [16][132]   A tile, k-major, padded
    float* invc = As + 16 * 132;        // [128]
    float* bias = invc + 128;           // [128]

    const int tid = threadIdx.x;
    const int block_row = blockIdx.x * 128;

    // stage combined weight into shared (float4)
    {
        float4* Wd = reinterpret_cast<float4*>(Ws);
        const float4* Wl4 = reinterpret_cast<const float4*>(Wl);
        const float4* Wr4 = reinterpret_cast<const float4*>(Wr);
        #pragma unroll 4
        for (int i = tid; i < 8192; i += 256)
            Wd[i] = (i < 4096) ? __ldg(&Wl4[i]) : __ldg(&Wr4[i - 4096]);
    }
    if (tid < 128) {
        int r = block_row + tid;
        int c = (r < N_NODES) ? d_counts[r] : 1;
        invc[tid] = 1.f / (float)max(c, 1);
        bias[tid] = bl[tid];
    }
    __syncthreads();

    const int tr = tid >> 4;   // 0..15 -> rows tr*8..tr*8+7
    const int tc = tid & 15;   // 0..15 -> cols tc*8..tc*8+7

    float acc[8][8];
    #pragma unroll
    for (int r = 0; r < 8; r++)
        #pragma unroll
        for (int c = 0; c < 8; c++) acc[r][c] = 0.f;

    for (int kt = 0; kt < 16; kt++) {
        // ---- load A tile [128 rows][16 k] transposed into As[k][row] ----
        #pragma unroll
        for (int i = 0; i < 2; i++) {
            int idx = tid + i * 256;
            int row = idx >> 2;      // 0..127
            int q   = idx & 3;       // float4 slot within 16-wide k tile
            int k   = kt * 16 + q * 4;
            int grow = block_row + row;
            float4 v = make_float4(0.f, 0.f, 0.f, 0.f);
            if (grow < N_NODES) {
                if (k < HID) {
                    v = __ldg(reinterpret_cast<const float4*>(&d_summed[(size_t)grow * HID + k]));
                    float ic = invc[row];
                    v.x *= ic; v.y *= ic; v.z *= ic; v.w *= ic;
                } else {
                    v = __ldg(reinterpret_cast<const float4*>(&x[(size_t)grow * HID + (k - HID)]));
                }
            }
            int kl = q * 4;
            As[(kl + 0) * 132 + row] = v.x;
            As[(kl + 1) * 132 + row] = v.y;
            As[(kl + 2) * 132 + row] = v.z;
            As[(kl + 3) * 132 + row] = v.w;
        }
        __syncthreads();

        // ---- compute 16 k-steps ----
        #pragma unroll
        for (int kk = 0; kk < 16; kk++) {
            float4 a0 = *reinterpret_cast<const float4*>(&As[kk * 132 + tr * 8]);
            float4 a1 = *reinterpret_cast<const float4*>(&As[kk * 132 + tr * 8 + 4]);
            const float* wrow = &Ws[(kt * 16 + kk) * 128 + tc * 8];
            float4 b0 = *reinterpret_cast<const float4*>(wrow);
            float4 b1 = *reinterpret_cast<const float4*>(wrow + 4);
            float a[8] = {a0.x, a0.y, a0.z, a0.w, a1.x, a1.y, a1.z, a1.w};
            float b[8] = {b0.x, b0.y, b0.z, b0.w, b1.x, b1.y, b1.z, b1.w};
            #pragma unroll
            for (int r = 0; r < 8; r++)
                #pragma unroll
                for (int c = 0; c < 8; c++)
                    acc[r][c] += a[r] * b[c];
        }
        __syncthreads();
    }

    // ---- epilogue: + bias, store h ----
    float bb[8];
    #pragma unroll
    for (int c = 0; c < 8; c++) bb[c] = bias[tc * 8 + c];

    #pragma unroll
    for (int r = 0; r < 8; r++) {
        int grow = block_row + tr * 8 + r;
        if (grow < N_NODES) {
            float4 o0, o1;
            o0.x = acc[r][0] + bb[0]; o0.y = acc[r][1] + bb[1];
            o0.z = acc[r][2] + bb[2]; o0.w = acc[r][3] + bb[3];
            o1.x = acc[r][4] + bb[4]; o1.y = acc[r][5] + bb[5];
            o1.z = acc[r][6] + bb[6]; o1.w = acc[r][7] + bb[7];
            *reinterpret_cast<float4*>(&d_h[(size_t)grow * HID + tc * 8])     = o0;
            *reinterpret_cast<float4*>(&d_h[(size_t)grow * HID + tc * 8 + 4]) = o1;
        }
    }
}

// ---------------- kernel 5: row-normalize h and project to classes ----------------
__global__ void classify_kernel(float* __restrict__ out) {
    __shared__ float Wn_s[HID * NUM_CLS];
    for (int i = threadIdx.x; i < HID * NUM_CLS; i += blockDim.x)
        Wn_s[i] = d_Wn[i];
    __syncthreads();

    int node = blockIdx.x * blockDim.x + threadIdx.x;
    if (node >= N_NODES) return;

    const float4* hp = reinterpret_cast<const float4*>(&d_h[(size_t)node * HID]);
    float acc[NUM_CLS];
    #pragma unroll
    for (int c = 0; c < NUM_CLS; c++) acc[c] = 0.f;
    float ss = 0.f;

    #pragma unroll 4
    for (int j4 = 0; j4 < HID / 4; j4++) {
        float4 v = __ldg(&hp[j4]);
        ss += v.x * v.x + v.y * v.y + v.z * v.z + v.w * v.w;
        int j = j4 * 4;
        #pragma unroll
        for (int c = 0; c < NUM_CLS; c++) {
            acc[c] += v.x * Wn_s[(j + 0) * NUM_CLS + c]
                    + v.y * Wn_s[(j + 1) * NUM_CLS + c]
                    + v.z * Wn_s[(j + 2) * NUM_CLS + c]
                    + v.w * Wn_s[(j + 3) * NUM_CLS + c];
        }
    }
    float inv = 1.f / fmaxf(sqrtf(ss), 1e-12f);
    #pragma unroll
    for (int c = 0; c < NUM_CLS; c++)
        out[node * NUM_CLS + c] = acc[c] * inv;
}

// ---------------- launch ----------------
extern "C" void kernel_launch(void* const* d_in, const int* in_sizes, int n_in,
                              void* d_out, int out_size) {
    const float* x   = (const float*)d_in[0];
    const int*   ei  = (const int*)d_in[1];     // int32 (JAX demotes int64)
    const float* Wl  = (const float*)d_in[2];
    const float* bl  = (const float*)d_in[3];
    const float* Wr  = (const float*)d_in[4];
    const float* Wc  = (const float*)d_in[5];
    float*       out = (float*)d_out;

    const int smem_bytes = SMEM_FLOATS * (int)sizeof(float);
    cudaFuncSetAttribute(gemm_kernel, cudaFuncAttributeMaxDynamicSharedMemorySize,
                         smem_bytes);

    zero_kernel<<<1024, 256>>>();
    normw_kernel<<<1, 32>>>(Wc);
    {
        // one warp per edge
        long long total_threads = (long long)N_EDGES * 32;
        int blocks = (int)((total_threads + 255) / 256);
        scatter_kernel<<<blocks, 256>>>(x, ei);
    }
    gemm_kernel<<<(N_NODES + 127) / 128, 256, smem_bytes>>>(x, Wl, bl, Wr);
    classify_kernel<<<(N_NODES + 255) / 256, 256>>>(out);
}

// round 7
// speedup vs baseline: 1.6993x; 1.6993x over previous
#include <cuda_runtime.h>
#include <cuda_bf16.h>
#include <cstdint>
#include <math.h>

#define N_NODES 100000
#define HID     128
#define NUM_CLS 20
#define N_EDGES 625000

// ---------------- scratch (static device globals; no allocation) ----------------
__device__ float d_summed[N_NODES * HID];          // 51.2 MB
__device__ int   d_counts[N_NODES];
__device__ __nv_bfloat16 d_Bhi[128 * 256];         // weight^T bf16-hi  [n][k]
__device__ __nv_bfloat16 d_Blo[128 * 256];         // weight^T bf16-lo  [n][k]
__device__ float d_Wn[HID * NUM_CLS];              // col-normalized classifier weight

// ---------------- kernel 1: zero scratch ----------------
__global__ void zero_kernel() {
    int idx = blockIdx.x * blockDim.x + threadIdx.x;
    int stride = gridDim.x * blockDim.x;
    float4* s4 = reinterpret_cast<float4*>(d_summed);
    const int n4 = N_NODES * HID / 4;
    for (int i = idx; i < n4; i += stride) s4[i] = make_float4(0.f, 0.f, 0.f, 0.f);
    for (int i = idx; i < N_NODES; i += stride) d_counts[i] = 0;
}

// ---------------- kernel 2: column-normalize W_cls ----------------
__global__ void normw_kernel(const float* __restrict__ Wc) {
    int c = threadIdx.x;
    if (c >= NUM_CLS) return;
    float s = 0.f;
    for (int j = 0; j < HID; j++) {
        float v = Wc[j * NUM_CLS + c];
        s += v * v;
    }
    float inv = 1.f / fmaxf(sqrtf(s), 1e-12f);
    for (int j = 0; j < HID; j++)
        d_Wn[j * NUM_CLS + c] = Wc[j * NUM_CLS + c] * inv;
}

// ---------------- kernel 2b: B = [W_l;W_r]^T split into bf16 hi/lo ----------------
__global__ void prepB_kernel(const float* __restrict__ Wl, const float* __restrict__ Wr) {
    int n = blockIdx.x;    // 0..127 output col
    int k = threadIdx.x;   // 0..255
    float w = (k < 128) ? Wl[k * 128 + n] : Wr[(k - 128) * 128 + n];
    __nv_bfloat16 hi = __float2bfloat16_rn(w);
    __nv_bfloat16 lo = __float2bfloat16_rn(w - __bfloat162float(hi));
    d_Bhi[n * 256 + k] = hi;
    d_Blo[n * 256 + k] = lo;
}

// ---------------- kernel 3: edge scatter (warp per edge, int32 indices) ----------------
__global__ void scatter_kernel(const float* __restrict__ x, const int* __restrict__ ei) {
    int gw   = (blockIdx.x * blockDim.x + threadIdx.x) >> 5;
    int lane = threadIdx.x & 31;
    if (gw >= N_EDGES) return;
    int src = __ldg(&ei[gw]);
    int dst = __ldg(&ei[N_EDGES + gw]);
    const float4* xp = reinterpret_cast<const float4*>(x + (size_t)src * HID);
    float4 v = __ldg(xp + lane);
    float* p = d_summed + (size_t)dst * HID + lane * 4;
    asm volatile("red.global.add.v4.f32 [%0], {%1,%2,%3,%4};"
                 :: "l"(p), "f"(v.x), "f"(v.y), "f"(v.z), "f"(v.w) : "memory");
    if (lane == 0) atomicAdd(&d_counts[dst], 1);
}

// ---------------- kernel 4: mma.sync bf16-split GEMM + fused normalize/classify ------
// C[128,128] = A[128,256] @ B^T;  A = (summed*invc | x) split hi/lo bf16.
// Products hi*hi + hi*lo + lo*hi via mma.sync.m16n8k16.bf16 (sm_100-legal HMMA).
// 8 warps: 4x2 grid of 32x64 warp tiles. Epilogue: C -> smem, per-row normalize
// + 20-class projection, write out directly.

// smem byte offsets
#define SM_AHI   0          // 128 x 24(bf16 stride) x 2B = 6144
#define SM_ALO   6144
#define SM_BHI   12288
#define SM_BLO   18432      // stage region ends 24576
#define SM_C     0          // reuses stage region after mainloop: 128*129*4 = 66048
#define SM_WN    66048      // 128*20*4 = 10240
#define SM_BIAS  76288      // 512
#define SM_INVC  76800      // 512
#define SM_PART  77312      // 128*21*4 = 10752 -> total 88064
#define GEMM_SMEM_BYTES 88064

__device__ __forceinline__ void mma_bf16(float* c, const uint32_t* a, uint32_t b0, uint32_t b1) {
    asm volatile("mma.sync.aligned.m16n8k16.row.col.f32.bf16.bf16.f32 "
                 "{%0,%1,%2,%3}, {%4,%5,%6,%7}, {%8,%9}, {%0,%1,%2,%3};"
                 : "+f"(c[0]), "+f"(c[1]), "+f"(c[2]), "+f"(c[3])
                 : "r"(a[0]), "r"(a[1]), "r"(a[2]), "r"(a[3]), "r"(b0), "r"(b1));
}

__global__ __launch_bounds__(256, 2)
void gemm_mma_kernel(const float* __restrict__ x,
                     const float* __restrict__ bl,
                     float* __restrict__ out) {
    extern __shared__ char sm[];
    float* smf = reinterpret_cast<float*>(sm);
    const int tid  = threadIdx.x;
    const int wid  = tid >> 5;
    const int lane = tid & 31;
    const int g    = lane >> 2;   // group id (0..7)
    const int tig  = lane & 3;    // thread in group
    const int warp_m = wid >> 1;  // 0..3 -> rows warp_m*32
    const int warp_n = wid & 1;   // 0..1 -> cols warp_n*64
    const int rbase = warp_m * 32;
    const int cbase = warp_n * 64;
    const int block_row = blockIdx.x * 128;

    // ---- init: Wn, bias, invc ----
    for (int i = tid; i < HID * NUM_CLS; i += 256) smf[SM_WN / 4 + i] = d_Wn[i];
    if (tid < 128) {
        smf[SM_BIAS / 4 + tid] = __ldg(&bl[tid]);
        int r = block_row + tid;
        int cnt = (r < N_NODES) ? d_counts[r] : 1;
        smf[SM_INVC / 4 + tid] = 1.f / (float)max(cnt, 1);
    }
    __syncthreads();

    float acc[64];   // [mt(2)][j(8)][q(4)]
    #pragma unroll
    for (int i = 0; i < 64; i++) acc[i] = 0.f;

    // ---- mainloop: 16 chunks of 16 k ----
    for (int c = 0; c < 16; c++) {
        const int kb = c * 16;
        const bool left = (c < 8);

        // A stage: 128 rows x 16 k fp32 -> bf16 hi/lo (stride 24 bf16)
        #pragma unroll
        for (int i = 0; i < 2; i++) {
            int idx = tid + i * 256;       // 0..511
            int row = idx >> 2;
            int kq  = idx & 3;             // float4 within chunk
            int grow = block_row + row;
            float4 av = make_float4(0.f, 0.f, 0.f, 0.f);
            if (grow < N_NODES) {
                if (left) {
                    av = __ldg(reinterpret_cast<const float4*>(&d_summed[(size_t)grow * HID + kb + kq * 4]));
                    float ic = smf[SM_INVC / 4 + row];
                    av.x *= ic; av.y *= ic; av.z *= ic; av.w *= ic;
                } else {
                    av = __ldg(reinterpret_cast<const float4*>(&x[(size_t)grow * HID + (kb - 128) + kq * 4]));
                }
            }
            __nv_bfloat162 h01, h23, l01, l23;
            h01.x = __float2bfloat16_rn(av.x); h01.y = __float2bfloat16_rn(av.y);
            h23.x = __float2bfloat16_rn(av.z); h23.y = __float2bfloat16_rn(av.w);
            l01.x = __float2bfloat16_rn(av.x - __bfloat162float(h01.x));
            l01.y = __float2bfloat16_rn(av.y - __bfloat162float(h01.y));
            l23.x = __float2bfloat16_rn(av.z - __bfloat162float(h23.x));
            l23.y = __float2bfloat16_rn(av.w - __bfloat162float(h23.y));
            uint32_t off = (uint32_t)(row * 24 + kq * 4) * 2;   // bytes
            *reinterpret_cast<__nv_bfloat162*>(sm + SM_AHI + off)     = h01;
            *reinterpret_cast<__nv_bfloat162*>(sm + SM_AHI + off + 4) = h23;
            *reinterpret_cast<__nv_bfloat162*>(sm + SM_ALO + off)     = l01;
            *reinterpret_cast<__nv_bfloat162*>(sm + SM_ALO + off + 4) = l23;
        }
        // B stage: 128 n-rows x 16 k bf16 (hi & lo), 16B per thread
        {
            int row  = tid >> 1;
            int half = tid & 1;
            const char* gh = reinterpret_cast<const char*>(d_Bhi) + row * 512 + kb * 2 + half * 16;
            const char* gl = reinterpret_cast<const char*>(d_Blo) + row * 512 + kb * 2 + half * 16;
            uint4 vh = __ldg(reinterpret_cast<const uint4*>(gh));
            uint4 vl = __ldg(reinterpret_cast<const uint4*>(gl));
            *reinterpret_cast<uint4*>(sm + SM_BHI + row * 48 + half * 16) = vh;
            *reinterpret_cast<uint4*>(sm + SM_BLO + row * 48 + half * 16) = vl;
        }
        __syncthreads();

        // 3 products: hi*hi, hi*lo, lo*hi
        #pragma unroll
        for (int p = 0; p < 3; p++) {
            const char* sa = sm + ((p == 2) ? SM_ALO : SM_AHI);
            const char* sb = sm + ((p == 1) ? SM_BLO : SM_BHI);
            uint32_t afr[2][4];
            #pragma unroll
            for (int mt = 0; mt < 2; mt++) {
                int r0 = rbase + mt * 16 + g;
                afr[mt][0] = *reinterpret_cast<const uint32_t*>(sa + (r0 * 24 + tig * 2) * 2);
                afr[mt][1] = *reinterpret_cast<const uint32_t*>(sa + ((r0 + 8) * 24 + tig * 2) * 2);
                afr[mt][2] = *reinterpret_cast<const uint32_t*>(sa + (r0 * 24 + tig * 2 + 8) * 2);
                afr[mt][3] = *reinterpret_cast<const uint32_t*>(sa + ((r0 + 8) * 24 + tig * 2 + 8) * 2);
            }
            #pragma unroll
            for (int j = 0; j < 8; j++) {
                int nr = cbase + j * 8 + g;
                uint32_t b0 = *reinterpret_cast<const uint32_t*>(sb + (nr * 24 + tig * 2) * 2);
                uint32_t b1 = *reinterpret_cast<const uint32_t*>(sb + (nr * 24 + tig * 2 + 8) * 2);
                mma_bf16(&acc[(0 * 8 + j) * 4], afr[0], b0, b1);
                mma_bf16(&acc[(1 * 8 + j) * 4], afr[1], b0, b1);
            }
        }
        __syncthreads();
    }

    // ---- write C tile to smem (stride 129 floats) ----
    #pragma unroll
    for (int mt = 0; mt < 2; mt++) {
        #pragma unroll
        for (int j = 0; j < 8; j++) {
            int r0  = rbase + mt * 16 + g;
            int col = cbase + j * 8 + tig * 2;
            const float* a4 = &acc[(mt * 8 + j) * 4];
            smf[SM_C / 4 + r0 * 129 + col]           = a4[0];
            smf[SM_C / 4 + r0 * 129 + col + 1]       = a4[1];
            smf[SM_C / 4 + (r0 + 8) * 129 + col]     = a4[2];
            smf[SM_C / 4 + (r0 + 8) * 129 + col + 1] = a4[3];
        }
    }
    __syncthreads();

    // ---- fused epilogue: half-rows, normalize + project ----
    {
        int half = tid >> 7;           // 0: cols 0-63, 1: cols 64-127
        int row  = tid & 127;
        int cb   = half * 64;
        float ss = 0.f;
        float a20[NUM_CLS];
        #pragma unroll
        for (int k = 0; k < NUM_CLS; k++) a20[k] = 0.f;

        #pragma unroll 4
        for (int j = 0; j < 64; j++) {
            int col = cb + j;
            float h = smf[SM_C / 4 + row * 129 + col] + smf[SM_BIAS / 4 + col];
            ss += h * h;
            const float4* wr = reinterpret_cast<const float4*>(&smf[SM_WN / 4 + col * NUM_CLS]);
            float4 w0 = wr[0], w1 = wr[1], w2 = wr[2], w3 = wr[3], w4 = wr[4];
            a20[0]  += h * w0.x; a20[1]  += h * w0.y; a20[2]  += h * w0.z; a20[3]  += h * w0.w;
            a20[4]  += h * w1.x; a20[5]  += h * w1.y; a20[6]  += h * w1.z; a20[7]  += h * w1.w;
            a20[8]  += h * w2.x; a20[9]  += h * w2.y; a20[10] += h * w2.z; a20[11] += h * w2.w;
            a20[12] += h * w3.x; a20[13] += h * w3.y; a20[14] += h * w3.z; a20[15] += h * w3.w;
            a20[16] += h * w4.x; a20[17] += h * w4.y; a20[18] += h * w4.z; a20[19] += h * w4.w;
        }
        if (half == 1) {
            float* pp = &smf[SM_PART / 4 + row * 21];
            pp[0] = ss;
            #pragma unroll
            for (int k = 0; k < NUM_CLS; k++) pp[1 + k] = a20[k];
        }
        __syncthreads();
        if (half == 0) {
            const float* pp = &smf[SM_PART / 4 + row * 21];
            ss += pp[0];
            #pragma unroll
            for (int k = 0; k < NUM_CLS; k++) a20[k] += pp[1 + k];
            int grow = block_row + row;
            if (grow < N_NODES) {
                float inv = 1.f / fmaxf(sqrtf(ss), 1e-12f);
                float* op = out + (size_t)grow * NUM_CLS;
                #pragma unroll
                for (int q = 0; q < 5; q++) {
                    float4 o;
                    o.x = a20[q * 4 + 0] * inv; o.y = a20[q * 4 + 1] * inv;
                    o.z = a20[q * 4 + 2] * inv; o.w = a20[q * 4 + 3] * inv;
                    *reinterpret_cast<float4*>(op + q * 4) = o;
                }
            }
        }
    }
}

// ---------------- launch ----------------
extern "C" void kernel_launch(void* const* d_in, const int* in_sizes, int n_in,
                              void* d_out, int out_size) {
    const float* x   = (const float*)d_in[0];
    const int*   ei  = (const int*)d_in[1];     // int32 (JAX demotes int64)
    const float* Wl  = (const float*)d_in[2];
    const float* bl  = (const float*)d_in[3];
    const float* Wr  = (const float*)d_in[4];
    const float* Wc  = (const float*)d_in[5];
    float*       out = (float*)d_out;

    cudaFuncSetAttribute(gemm_mma_kernel, cudaFuncAttributeMaxDynamicSharedMemorySize,
                         GEMM_SMEM_BYTES);

    zero_kernel<<<2048, 256>>>();
    normw_kernel<<<1, 32>>>(Wc);
    prepB_kernel<<<128, 256>>>(Wl, Wr);
    {
        long long total_threads = (long long)N_EDGES * 32;
        int blocks = (int)((total_threads + 255) / 256);
        scatter_kernel<<<blocks, 256>>>(x, ei);
    }
    gemm_mma_kernel<<<(N_NODES + 127) / 128, 256, GEMM_SMEM_BYTES>>>(x, bl, out);
}

// round 8
// speedup vs baseline: 1.9795x; 1.1649x over previous
#include <cuda_runtime.h>
#include <cuda_bf16.h>
#include <cstdint>
#include <math.h>

#define N_NODES 100000
#define HID     128
#define NUM_CLS 20
#define N_EDGES 625000
#define E_PER_WARP 4

// ---------------- scratch (static device globals; no allocation) ----------------
__device__ float d_summed[N_NODES * HID];          // 51.2 MB
__device__ int   d_counts[N_NODES];
__device__ __nv_bfloat16 d_Bhi[128 * 256];         // weight^T bf16-hi  [n][k]
__device__ __nv_bfloat16 d_Blo[128 * 256];         // weight^T bf16-lo  [n][k]
__device__ float d_Wn[HID * NUM_CLS];              // col-normalized classifier weight

// ---------------- kernel 1: zero scratch ----------------
__global__ void zero_kernel() {
    int idx = blockIdx.x * blockDim.x + threadIdx.x;
    int stride = gridDim.x * blockDim.x;
    float4* s4 = reinterpret_cast<float4*>(d_summed);
    const int n4 = N_NODES * HID / 4;
    for (int i = idx; i < n4; i += stride) s4[i] = make_float4(0.f, 0.f, 0.f, 0.f);
    for (int i = idx; i < N_NODES; i += stride) d_counts[i] = 0;
}

// ---------------- kernel 2: column-normalize W_cls ----------------
__global__ void normw_kernel(const float* __restrict__ Wc) {
    int c = threadIdx.x;
    if (c >= NUM_CLS) return;
    float s = 0.f;
    for (int j = 0; j < HID; j++) {
        float v = Wc[j * NUM_CLS + c];
        s += v * v;
    }
    float inv = 1.f / fmaxf(sqrtf(s), 1e-12f);
    for (int j = 0; j < HID; j++)
        d_Wn[j * NUM_CLS + c] = Wc[j * NUM_CLS + c] * inv;
}

// ---------------- kernel 2b: B = [W_l;W_r]^T split into bf16 hi/lo ----------------
__global__ void prepB_kernel(const float* __restrict__ Wl, const float* __restrict__ Wr) {
    int n = blockIdx.x;    // 0..127 output col
    int k = threadIdx.x;   // 0..255
    float w = (k < 128) ? Wl[k * 128 + n] : Wr[(k - 128) * 128 + n];
    __nv_bfloat16 hi = __float2bfloat16_rn(w);
    __nv_bfloat16 lo = __float2bfloat16_rn(w - __bfloat162float(hi));
    d_Bhi[n * 256 + k] = hi;
    d_Blo[n * 256 + k] = lo;
}

// ---------------- kernel 3: edge scatter, 4 edges/warp (MLP=4) ----------------
__global__ void scatter_kernel(const float* __restrict__ x, const int* __restrict__ ei) {
    int gw   = (blockIdx.x * blockDim.x + threadIdx.x) >> 5;
    int lane = threadIdx.x & 31;
    int e0 = gw * E_PER_WARP;
    if (e0 >= N_EDGES) return;

    int src[E_PER_WARP], dst[E_PER_WARP];
    #pragma unroll
    for (int i = 0; i < E_PER_WARP; i++) {
        int e = e0 + i;
        if (e < N_EDGES) {
            src[i] = __ldg(&ei[e]);
            dst[i] = __ldg(&ei[N_EDGES + e]);
        } else {
            src[i] = -1;
        }
    }
    // batch the gathers: independent LDG.128s in flight together
    float4 v[E_PER_WARP];
    #pragma unroll
    for (int i = 0; i < E_PER_WARP; i++)
        if (src[i] >= 0)
            v[i] = __ldg(reinterpret_cast<const float4*>(x + (size_t)src[i] * HID) + lane);
    #pragma unroll
    for (int i = 0; i < E_PER_WARP; i++) {
        if (src[i] >= 0) {
            float* p = d_summed + (size_t)dst[i] * HID + lane * 4;
            asm volatile("red.global.add.v4.f32 [%0], {%1,%2,%3,%4};"
                         :: "l"(p), "f"(v[i].x), "f"(v[i].y), "f"(v[i].z), "f"(v[i].w)
                         : "memory");
            if (lane == 0) atomicAdd(&d_counts[dst[i]], 1);
        }
    }
}

// ---------------- kernel 4: mma.sync bf16-split GEMM + fused normalize/classify ------
// C[128,128] = A[128,256] @ B^T;  A = (summed*invc | x) split hi/lo bf16.
// Products hi*hi + hi*lo + lo*hi via mma.sync.m16n8k16.bf16.
// Software-pipelined: chunk c+1 gmem loads issued before chunk c MMAs.

// smem byte offsets
#define SM_AHI   0          // 128 x 24(bf16 stride) x 2B = 6144
#define SM_ALO   6144
#define SM_BHI   12288
#define SM_BLO   18432      // stage region ends 24576
#define SM_C     0          // reuses stage region after mainloop: 128*129*4 = 66048
#define SM_WN    66048      // 128*20*4 = 10240
#define SM_BIAS  76288      // 512
#define SM_INVC  76800      // 512
#define SM_PART  77312      // 128*21*4 = 10752 -> total 88064
#define GEMM_SMEM_BYTES 88064

__device__ __forceinline__ void mma_bf16(float* c, const uint32_t* a, uint32_t b0, uint32_t b1) {
    asm volatile("mma.sync.aligned.m16n8k16.row.col.f32.bf16.bf16.f32 "
                 "{%0,%1,%2,%3}, {%4,%5,%6,%7}, {%8,%9}, {%0,%1,%2,%3};"
                 : "+f"(c[0]), "+f"(c[1]), "+f"(c[2]), "+f"(c[3])
                 : "r"(a[0]), "r"(a[1]), "r"(a[2]), "r"(a[3]), "r"(b0), "r"(b1));
}

__global__ __launch_bounds__(256, 2)
void gemm_mma_kernel(const float* __restrict__ x,
                     const float* __restrict__ bl,
                     float* __restrict__ out) {
    extern __shared__ char sm[];
    float* smf = reinterpret_cast<float*>(sm);
    const int tid  = threadIdx.x;
    const int wid  = tid >> 5;
    const int lane = tid & 31;
    const int g    = lane >> 2;   // group id (0..7)
    const int tig  = lane & 3;    // thread in group
    const int warp_m = wid >> 1;  // 0..3 -> rows warp_m*32
    const int warp_n = wid & 1;   // 0..1 -> cols warp_n*64
    const int rbase = warp_m * 32;
    const int cbase = warp_n * 64;
    const int block_row = blockIdx.x * 128;

    // per-thread A staging coords (2 float4 per thread per chunk)
    const int a_row0 = tid >> 2;            // idx = tid
    const int a_kq0  = tid & 3;
    const int a_row1 = (tid + 256) >> 2;    // idx = tid + 256
    const int a_kq1  = (tid + 256) & 3;
    // B staging coords (1 uint4 hi + 1 uint4 lo per thread per chunk)
    const int b_row  = tid >> 1;
    const int b_half = tid & 1;

    // ---- init: Wn, bias, invc ----
    for (int i = tid; i < HID * NUM_CLS; i += 256) smf[SM_WN / 4 + i] = d_Wn[i];
    if (tid < 128) {
        smf[SM_BIAS / 4 + tid] = __ldg(&bl[tid]);
        int r = block_row + tid;
        int cnt = (r < N_NODES) ? d_counts[r] : 1;
        smf[SM_INVC / 4 + tid] = 1.f / (float)max(cnt, 1);
    }
    __syncthreads();

    float acc[64];   // [mt(2)][j(8)][q(4)]
    #pragma unroll
    for (int i = 0; i < 64; i++) acc[i] = 0.f;

    // ---- prefetch chunk 0 into registers ----
    float4 av0, av1;
    uint4  vh, vl;
    {
        int grow0 = block_row + a_row0;
        int grow1 = block_row + a_row1;
        av0 = make_float4(0.f, 0.f, 0.f, 0.f);
        av1 = make_float4(0.f, 0.f, 0.f, 0.f);
        if (grow0 < N_NODES)
            av0 = __ldg(reinterpret_cast<const float4*>(&d_summed[(size_t)grow0 * HID + a_kq0 * 4]));
        if (grow1 < N_NODES)
            av1 = __ldg(reinterpret_cast<const float4*>(&d_summed[(size_t)grow1 * HID + a_kq1 * 4]));
        const char* gh = reinterpret_cast<const char*>(d_Bhi) + b_row * 512 + b_half * 16;
        const char* gl = reinterpret_cast<const char*>(d_Blo) + b_row * 512 + b_half * 16;
        vh = __ldg(reinterpret_cast<const uint4*>(gh));
        vl = __ldg(reinterpret_cast<const uint4*>(gl));
    }

    // ---- mainloop: 16 chunks of 16 k, register-pipelined ----
    for (int c = 0; c < 16; c++) {
        const bool left = (c < 8);

        // stage current chunk (registers -> smem, with invc scale + bf16 split)
        {
            float4 a = av0;
            if (left) {
                float ic = smf[SM_INVC / 4 + a_row0];
                a.x *= ic; a.y *= ic; a.z *= ic; a.w *= ic;
            }
            __nv_bfloat162 h01, h23, l01, l23;
            h01.x = __float2bfloat16_rn(a.x); h01.y = __float2bfloat16_rn(a.y);
            h23.x = __float2bfloat16_rn(a.z); h23.y = __float2bfloat16_rn(a.w);
            l01.x = __float2bfloat16_rn(a.x - __bfloat162float(h01.x));
            l01.y = __float2bfloat16_rn(a.y - __bfloat162float(h01.y));
            l23.x = __float2bfloat16_rn(a.z - __bfloat162float(h23.x));
            l23.y = __float2bfloat16_rn(a.w - __bfloat162float(h23.y));
            uint32_t off = (uint32_t)(a_row0 * 24 + a_kq0 * 4) * 2;
            *reinterpret_cast<__nv_bfloat162*>(sm + SM_AHI + off)     = h01;
            *reinterpret_cast<__nv_bfloat162*>(sm + SM_AHI + off + 4) = h23;
            *reinterpret_cast<__nv_bfloat162*>(sm + SM_ALO + off)     = l01;
            *reinterpret_cast<__nv_bfloat162*>(sm + SM_ALO + off + 4) = l23;
        }
        {
            float4 a = av1;
            if (left) {
                float ic = smf[SM_INVC / 4 + a_row1];
                a.x *= ic; a.y *= ic; a.z *= ic; a.w *= ic;
            }
            __nv_bfloat162 h01, h23, l01, l23;
            h01.x = __float2bfloat16_rn(a.x); h01.y = __float2bfloat16_rn(a.y);
            h23.x = __float2bfloat16_rn(a.z); h23.y = __float2bfloat16_rn(a.w);
            l01.x = __float2bfloat16_rn(a.x - __bfloat162float(h01.x));
            l01.y = __float2bfloat16_rn(a.y - __bfloat162float(h01.y));
            l23.x = __float2bfloat16_rn(a.z - __bfloat162float(h23.x));
            l23.y = __float2bfloat16_rn(a.w - __bfloat162float(h23.y));
            uint32_t off = (uint32_t)(a_row1 * 24 + a_kq1 * 4) * 2;
            *reinterpret_cast<__nv_bfloat162*>(sm + SM_AHI + off)     = h01;
            *reinterpret_cast<__nv_bfloat162*>(sm + SM_AHI + off + 4) = h23;
            *reinterpret_cast<__nv_bfloat162*>(sm + SM_ALO + off)     = l01;
            *reinterpret_cast<__nv_bfloat162*>(sm + SM_ALO + off + 4) = l23;
        }
        *reinterpret_cast<uint4*>(sm + SM_BHI + b_row * 48 + b_half * 16) = vh;
        *reinterpret_cast<uint4*>(sm + SM_BLO + b_row * 48 + b_half * 16) = vl;
        __syncthreads();

        // issue next chunk's gmem loads BEFORE the MMA block (overlap latency)
        if (c < 15) {
            const int cn = c + 1;
            const int kb = cn * 16;
            const bool leftn = (cn < 8);
            int grow0 = block_row + a_row0;
            int grow1 = block_row + a_row1;
            av0 = make_float4(0.f, 0.f, 0.f, 0.f);
            av1 = make_float4(0.f, 0.f, 0.f, 0.f);
            if (grow0 < N_NODES) {
                const float* base = leftn ? &d_summed[(size_t)grow0 * HID + kb]
                                          : &x[(size_t)grow0 * HID + (kb - 128)];
                av0 = __ldg(reinterpret_cast<const float4*>(base + a_kq0 * 4));
            }
            if (grow1 < N_NODES) {
                const float* base = leftn ? &d_summed[(size_t)grow1 * HID + kb]
                                          : &x[(size_t)grow1 * HID + (kb - 128)];
                av1 = __ldg(reinterpret_cast<const float4*>(base + a_kq1 * 4));
            }
            const char* gh = reinterpret_cast<const char*>(d_Bhi) + b_row * 512 + kb * 2 + b_half * 16;
            const char* gl = reinterpret_cast<const char*>(d_Blo) + b_row * 512 + kb * 2 + b_half * 16;
            vh = __ldg(reinterpret_cast<const uint4*>(gh));
            vl = __ldg(reinterpret_cast<const uint4*>(gl));
        }

        // 3 products: hi*hi, hi*lo, lo*hi
        #pragma unroll
        for (int p = 0; p < 3; p++) {
            const char* sa = sm + ((p == 2) ? SM_ALO : SM_AHI);
            const char* sb = sm + ((p == 1) ? SM_BLO : SM_BHI);
            uint32_t afr[2][4];
            #pragma unroll
            for (int mt = 0; mt < 2; mt++) {
                int r0 = rbase + mt * 16 + g;
                afr[mt][0] = *reinterpret_cast<const uint32_t*>(sa + (r0 * 24 + tig * 2) * 2);
                afr[mt][1] = *reinterpret_cast<const uint32_t*>(sa + ((r0 + 8) * 24 + tig * 2) * 2);
                afr[mt][2] = *reinterpret_cast<const uint32_t*>(sa + (r0 * 24 + tig * 2 + 8) * 2);
                afr[mt][3] = *reinterpret_cast<const uint32_t*>(sa + ((r0 + 8) * 24 + tig * 2 + 8) * 2);
            }
            #pragma unroll
            for (int j = 0; j < 8; j++) {
                int nr = cbase + j * 8 + g;
                uint32_t b0 = *reinterpret_cast<const uint32_t*>(sb + (nr * 24 + tig * 2) * 2);
                uint32_t b1 = *reinterpret_cast<const uint32_t*>(sb + (nr * 24 + tig * 2 + 8) * 2);
                mma_bf16(&acc[(0 * 8 + j) * 4], afr[0], b0, b1);
                mma_bf16(&acc[(1 * 8 + j) * 4], afr[1], b0, b1);
            }
        }
        __syncthreads();
    }

    // ---- write C tile to smem (stride 129 floats) ----
    #pragma unroll
    for (int mt = 0; mt < 2; mt++) {
        #pragma unroll
        for (int j = 0; j < 8; j++) {
            int r0  = rbase + mt * 16 + g;
            int col = cbase + j * 8 + tig * 2;
            const float* a4 = &acc[(mt * 8 + j) * 4];
            smf[SM_C / 4 + r0 * 129 + col]           = a4[0];
            smf[SM_C / 4 + r0 * 129 + col + 1]       = a4[1];
            smf[SM_C / 4 + (r0 + 8) * 129 + col]     = a4[2];
            smf[SM_C / 4 + (r0 + 8) * 129 + col + 1] = a4[3];
        }
    }
    __syncthreads();

    // ---- fused epilogue: half-rows, normalize + project ----
    {
        int half = tid >> 7;           // 0: cols 0-63, 1: cols 64-127
        int row  = tid & 127;
        int cb   = half * 64;
        float ss = 0.f;
        float a20[NUM_CLS];
        #pragma unroll
        for (int k = 0; k < NUM_CLS; k++) a20[k] = 0.f;

        #pragma unroll 4
        for (int j = 0; j < 64; j++) {
            int col = cb + j;
            float h = smf[SM_C / 4 + row * 129 + col] + smf[SM_BIAS / 4 + col];
            ss += h * h;
            const float4* wr = reinterpret_cast<const float4*>(&smf[SM_WN / 4 + col * NUM_CLS]);
            float4 w0 = wr[0], w1 = wr[1], w2 = wr[2], w3 = wr[3], w4 = wr[4];
            a20[0]  += h * w0.x; a20[1]  += h * w0.y; a20[2]  += h * w0.z; a20[3]  += h * w0.w;
            a20[4]  += h * w1.x; a20[5]  += h * w1.y; a20[6]  += h * w1.z; a20[7]  += h * w1.w;
            a20[8]  += h * w2.x; a20[9]  += h * w2.y; a20[10] += h * w2.z; a20[11] += h * w2.w;
            a20[12] += h * w3.x; a20[13] += h * w3.y; a20[14] += h * w3.z; a20[15] += h * w3.w;
            a20[16] += h * w4.x; a20[17] += h * w4.y; a20[18] += h * w4.z; a20[19] += h * w4.w;
        }
        if (half == 1) {
            float* pp = &smf[SM_PART / 4 + row * 21];
            pp[0] = ss;
            #pragma unroll
            for (int k = 0; k < NUM_CLS; k++) pp[1 + k] = a20[k];
        }
        __syncthreads();
        if (half == 0) {
            const float* pp = &smf[SM_PART / 4 + row * 21];
            ss += pp[0];
            #pragma unroll
            for (int k = 0; k < NUM_CLS; k++) a20[k] += pp[1 + k];
            int grow = block_row + row;
            if (grow < N_NODES) {
                float inv = 1.f / fmaxf(sqrtf(ss), 1e-12f);
                float* op = out + (size_t)grow * NUM_CLS;
                #pragma unroll
                for (int q = 0; q < 5; q++) {
                    float4 o;
                    o.x = a20[q * 4 + 0] * inv; o.y = a20[q * 4 + 1] * inv;
                    o.z = a20[q * 4 + 2] * inv; o.w = a20[q * 4 + 3] * inv;
                    *reinterpret_cast<float4*>(op + q * 4) = o;
                }
            }
        }
    }
}

// ---------------- launch ----------------
extern "C" void kernel_launch(void* const* d_in, const int* in_sizes, int n_in,
                              void* d_out, int out_size) {
    const float* x   = (const float*)d_in[0];
    const int*   ei  = (const int*)d_in[1];     // int32 (JAX demotes int64)
    const float* Wl  = (const float*)d_in[2];
    const float* bl  = (const float*)d_in[3];
    const float* Wr  = (const float*)d_in[4];
    const float* Wc  = (const float*)d_in[5];
    float*       out = (float*)d_out;

    cudaFuncSetAttribute(gemm_mma_kernel, cudaFuncAttributeMaxDynamicSharedMemorySize,
                         GEMM_SMEM_BYTES);

    zero_kernel<<<2048, 256>>>();
    normw_kernel<<<1, 32>>>(Wc);
    prepB_kernel<<<128, 256>>>(Wl, Wr);
    {
        int warps = (N_EDGES + E_PER_WARP - 1) / E_PER_WARP;
        long long total_threads = (long long)warps * 32;
        int blocks = (int)((total_threads + 255) / 256);
        scatter_kernel<<<blocks, 256>>>(x, ei);
    }
    gemm_mma_kernel<<<(N_NODES + 127) / 128, 256, GEMM_SMEM_BYTES>>>(x, bl, out);
}

// round 10
// speedup vs baseline: 2.0222x; 1.0216x over previous
#include <cuda_runtime.h>
#include <cuda_bf16.h>
#include <cstdint>
#include <math.h>

#define N_NODES 100000
#define HID     128
#define NUM_CLS 20
#define N_EDGES 625000
#define E_PER_WARP 8

// ---------------- scratch (static device globals; no allocation) ----------------
__device__ float d_summed[N_NODES * HID];          // 51.2 MB
__device__ int   d_counts[N_NODES];
__device__ __nv_bfloat16 d_Bhi[128 * 256];         // weight^T bf16-hi  [n][k]
__device__ __nv_bfloat16 d_Blo[128 * 256];         // weight^T bf16-lo  [n][k]
__device__ float d_Wn[HID * NUM_CLS];              // col-normalized classifier weight

__device__ __forceinline__ uint32_t smem_u32(const void* p) {
    uint32_t a;
    asm("{ .reg .u64 t; cvta.to.shared.u64 t, %1; cvt.u32.u64 %0, t; }" : "=r"(a) : "l"(p));
    return a;
}

// ---------------- kernel 1: zero scratch ----------------
__global__ void zero_kernel() {
    int idx = blockIdx.x * blockDim.x + threadIdx.x;
    int stride = gridDim.x * blockDim.x;
    float4* s4 = reinterpret_cast<float4*>(d_summed);
    const int n4 = N_NODES * HID / 4;
    for (int i = idx; i < n4; i += stride) s4[i] = make_float4(0.f, 0.f, 0.f, 0.f);
    for (int i = idx; i < N_NODES; i += stride) d_counts[i] = 0;
}

// ---------------- kernel 2: column-normalize W_cls ----------------
__global__ void normw_kernel(const float* __restrict__ Wc) {
    int c = threadIdx.x;
    if (c >= NUM_CLS) return;
    float s = 0.f;
    for (int j = 0; j < HID; j++) {
        float v = Wc[j * NUM_CLS + c];
        s += v * v;
    }
    float inv = 1.f / fmaxf(sqrtf(s), 1e-12f);
    for (int j = 0; j < HID; j++)
        d_Wn[j * NUM_CLS + c] = Wc[j * NUM_CLS + c] * inv;
}

// ---------------- kernel 2b: B = [W_l;W_r]^T split into bf16 hi/lo ----------------
__global__ void prepB_kernel(const float* __restrict__ Wl, const float* __restrict__ Wr) {
    int n = blockIdx.x;    // 0..127 output col
    int k = threadIdx.x;   // 0..255
    float w = (k < 128) ? Wl[k * 128 + n] : Wr[(k - 128) * 128 + n];
    __nv_bfloat16 hi = __float2bfloat16_rn(w);
    __nv_bfloat16 lo = __float2bfloat16_rn(w - __bfloat162float(hi));
    d_Bhi[n * 256 + k] = hi;
    d_Blo[n * 256 + k] = lo;
}

// ---------------- kernel 3: edge scatter, 8 edges/warp (MLP=8) ----------------
__global__ void scatter_kernel(const float* __restrict__ x, const int* __restrict__ ei) {
    int gw   = (blockIdx.x * blockDim.x + threadIdx.x) >> 5;
    int lane = threadIdx.x & 31;
    int e0 = gw * E_PER_WARP;
    if (e0 >= N_EDGES) return;

    int src[E_PER_WARP], dst[E_PER_WARP];
    #pragma unroll
    for (int i = 0; i < E_PER_WARP; i++) {
        int e = e0 + i;
        if (e < N_EDGES) {
            src[i] = __ldg(&ei[e]);
            dst[i] = __ldg(&ei[N_EDGES + e]);
        } else {
            src[i] = -1;
        }
    }
    float4 v[E_PER_WARP];
    #pragma unroll
    for (int i = 0; i < E_PER_WARP; i++)
        if (src[i] >= 0)
            v[i] = __ldg(reinterpret_cast<const float4*>(x + (size_t)src[i] * HID) + lane);
    #pragma unroll
    for (int i = 0; i < E_PER_WARP; i++) {
        if (src[i] >= 0) {
            float* p = d_summed + (size_t)dst[i] * HID + lane * 4;
            asm volatile("red.global.add.v4.f32 [%0], {%1,%2,%3,%4};"
                         :: "l"(p), "f"(v[i].x), "f"(v[i].y), "f"(v[i].z), "f"(v[i].w)
                         : "memory");
            if (lane == 0) atomicAdd(&d_counts[dst[i]], 1);
        }
    }
}

// ---------------- kernel 4: mma.sync bf16-split GEMM (ldmatrix) + fused epilogue ------
// smem byte offsets
#define SM_AHI   0          // 128 x 24(bf16 stride) x 2B = 6144
#define SM_ALO   6144
#define SM_BHI   12288
#define SM_BLO   18432      // stage region ends 24576
#define SM_C     0          // reuses stage region after mainloop: 128*129*4 = 66048
#define SM_WN    66048      // 128*20*4 = 10240
#define SM_BIAS  76288      // 512
#define SM_INVC  76800      // 512
#define SM_PART  77312      // 128*21*4 = 10752 -> total 88064
#define GEMM_SMEM_BYTES 88064

__device__ __forceinline__ void mma_bf16(float* c, const uint32_t* a, uint32_t b0, uint32_t b1) {
    asm volatile("mma.sync.aligned.m16n8k16.row.col.f32.bf16.bf16.f32 "
                 "{%0,%1,%2,%3}, {%4,%5,%6,%7}, {%8,%9}, {%0,%1,%2,%3};"
                 : "+f"(c[0]), "+f"(c[1]), "+f"(c[2]), "+f"(c[3])
                 : "r"(a[0]), "r"(a[1]), "r"(a[2]), "r"(a[3]), "r"(b0), "r"(b1));
}
#define LDMX4(r, addr) \
    asm volatile("ldmatrix.sync.aligned.m8n8.x4.shared.b16 {%0,%1,%2,%3}, [%4];" \
                 : "=r"((r)[0]), "=r"((r)[1]), "=r"((r)[2]), "=r"((r)[3]) : "r"(addr))

__global__ __launch_bounds__(256, 2)
void gemm_mma_kernel(const float* __restrict__ x,
                     const float* __restrict__ bl,
                     float* __restrict__ out) {
    extern __shared__ char sm[];
    float* smf = reinterpret_cast<float*>(sm);
    const uint32_t sb32 = smem_u32(sm);
    const int tid  = threadIdx.x;
    const int wid  = tid >> 5;
    const int lane = tid & 31;
    const int g    = lane >> 2;
    const int tig  = lane & 3;
    const int warp_m = wid >> 1;  // 0..3 -> rows warp_m*32
    const int warp_n = wid & 1;   // 0..1 -> cols warp_n*64
    const int rbase = warp_m * 32;
    const int cbase = warp_n * 64;
    const int block_row = blockIdx.x * 128;

    // ldmatrix per-lane source coords (mat = lane>>3, rin = lane&7)
    const int lm_mat = lane >> 3;
    const int lm_rin = lane & 7;
    // A: mat0=(m,k0) mat1=(m+8,k0) mat2=(m,k8) mat3=(m+8,k8)
    const uint32_t a_off0 = (uint32_t)(((rbase + lm_rin + (lm_mat & 1) * 8) * 24 + (lm_mat >> 1) * 8) * 2);
    const uint32_t a_off1 = a_off0 + 16 * 24 * 2;   // mt=1 tile (+16 rows)
    // B: for j-pair j2: mat0=(j,k0) mat1=(j,k8) mat2=(j+1,k0) mat3=(j+1,k8)
    const uint32_t b_off  = (uint32_t)(((cbase + (lm_mat >> 1) * 8 + lm_rin) * 24 + (lm_mat & 1) * 8) * 2);

    // per-thread A staging coords (2 float4 per thread per chunk)
    const int a_row0 = tid >> 2;
    const int a_kq0  = tid & 3;
    const int a_row1 = (tid + 256) >> 2;
    const int a_kq1  = (tid + 256) & 3;
    // B staging coords
    const int b_row  = tid >> 1;
    const int b_half = tid & 1;

    // ---- init: Wn, bias, invc ----
    for (int i = tid; i < HID * NUM_CLS; i += 256) smf[SM_WN / 4 + i] = d_Wn[i];
    if (tid < 128) {
        smf[SM_BIAS / 4 + tid] = __ldg(&bl[tid]);
        int r = block_row + tid;
        int cnt = (r < N_NODES) ? d_counts[r] : 1;
        smf[SM_INVC / 4 + tid] = 1.f / (float)max(cnt, 1);
    }
    __syncthreads();

    float acc[64];   // [mt(2)][j(8)][q(4)]
    #pragma unroll
    for (int i = 0; i < 64; i++) acc[i] = 0.f;

    // ---- prefetch chunk 0 ----
    float4 av0, av1;
    uint4  vh, vl;
    {
        int grow0 = block_row + a_row0;
        int grow1 = block_row + a_row1;
        av0 = make_float4(0.f, 0.f, 0.f, 0.f);
        av1 = make_float4(0.f, 0.f, 0.f, 0.f);
        if (grow0 < N_NODES)
            av0 = __ldg(reinterpret_cast<const float4*>(&d_summed[(size_t)grow0 * HID + a_kq0 * 4]));
        if (grow1 < N_NODES)
            av1 = __ldg(reinterpret_cast<const float4*>(&d_summed[(size_t)grow1 * HID + a_kq1 * 4]));
        const char* gh = reinterpret_cast<const char*>(d_Bhi) + b_row * 512 + b_half * 16;
        const char* gl = reinterpret_cast<const char*>(d_Blo) + b_row * 512 + b_half * 16;
        vh = __ldg(reinterpret_cast<const uint4*>(gh));
        vl = __ldg(reinterpret_cast<const uint4*>(gl));
    }

    // ---- mainloop: 16 chunks of 16 k, register-pipelined ----
    for (int c = 0; c < 16; c++) {
        const bool left = (c < 8);

        // stage current chunk
        {
            float4 a = av0;
            if (left) {
                float ic = smf[SM_INVC / 4 + a_row0];
                a.x *= ic; a.y *= ic; a.z *= ic; a.w *= ic;
            }
            __nv_bfloat162 h01, h23, l01, l23;
            h01.x = __float2bfloat16_rn(a.x); h01.y = __float2bfloat16_rn(a.y);
            h23.x = __float2bfloat16_rn(a.z); h23.y = __float2bfloat16_rn(a.w);
            l01.x = __float2bfloat16_rn(a.x - __bfloat162float(h01.x));
            l01.y = __float2bfloat16_rn(a.y - __bfloat162float(h01.y));
            l23.x = __float2bfloat16_rn(a.z - __bfloat162float(h23.x));
            l23.y = __float2bfloat16_rn(a.w - __bfloat162float(h23.y));
            uint32_t off = (uint32_t)(a_row0 * 24 + a_kq0 * 4) * 2;
            *reinterpret_cast<__nv_bfloat162*>(sm + SM_AHI + off)     = h01;
            *reinterpret_cast<__nv_bfloat162*>(sm + SM_AHI + off + 4) = h23;
            *reinterpret_cast<__nv_bfloat162*>(sm + SM_ALO + off)     = l01;
            *reinterpret_cast<__nv_bfloat162*>(sm + SM_ALO + off + 4) = l23;
        }
        {
            float4 a = av1;
            if (left) {
                float ic = smf[SM_INVC / 4 + a_row1];
                a.x *= ic; a.y *= ic; a.z *= ic; a.w *= ic;
            }
            __nv_bfloat162 h01, h23, l01, l23;
            h01.x = __float2bfloat16_rn(a.x); h01.y = __float2bfloat16_rn(a.y);
            h23.x = __float2bfloat16_rn(a.z); h23.y = __float2bfloat16_rn(a.w);
            l01.x = __float2bfloat16_rn(a.x - __bfloat162float(h01.x));
            l01.y = __float2bfloat16_rn(a.y - __bfloat162float(h01.y));
            l23.x = __float2bfloat16_rn(a.z - __bfloat162float(h23.x));
            l23.y = __float2bfloat16_rn(a.w - __bfloat162float(h23.y));
            uint32_t off = (uint32_t)(a_row1 * 24 + a_kq1 * 4) * 2;
            *reinterpret_cast<__nv_bfloat162*>(sm + SM_AHI + off)     = h01;
            *reinterpret_cast<__nv_bfloat162*>(sm + SM_AHI + off + 4) = h23;
            *reinterpret_cast<__nv_bfloat162*>(sm + SM_ALO + off)     = l01;
            *reinterpret_cast<__nv_bfloat162*>(sm + SM_ALO + off + 4) = l23;
        }
        *reinterpret_cast<uint4*>(sm + SM_BHI + b_row * 48 + b_half * 16) = vh;
        *reinterpret_cast<uint4*>(sm + SM_BLO + b_row * 48 + b_half * 16) = vl;
        __syncthreads();

        // prefetch next chunk during MMAs
        if (c < 15) {
            const int cn = c + 1;
            const int kb = cn * 16;
            const bool leftn = (cn < 8);
            int grow0 = block_row + a_row0;
            int grow1 = block_row + a_row1;
            av0 = make_float4(0.f, 0.f, 0.f, 0.f);
            av1 = make_float4(0.f, 0.f, 0.f, 0.f);
            if (grow0 < N_NODES) {
                const float* base = leftn ? &d_summed[(size_t)grow0 * HID + kb]
                                          : &x[(size_t)grow0 * HID + (kb - 128)];
                av0 = __ldg(reinterpret_cast<const float4*>(base + a_kq0 * 4));
            }
            if (grow1 < N_NODES) {
                const float* base = leftn ? &d_summed[(size_t)grow1 * HID + kb]
                                          : &x[(size_t)grow1 * HID + (kb - 128)];
                av1 = __ldg(reinterpret_cast<const float4*>(base + a_kq1 * 4));
            }
            const char* gh = reinterpret_cast<const char*>(d_Bhi) + b_row * 512 + kb * 2 + b_half * 16;
            const char* gl = reinterpret_cast<const char*>(d_Blo) + b_row * 512 + kb * 2 + b_half * 16;
            vh = __ldg(reinterpret_cast<const uint4*>(gh));
            vl = __ldg(reinterpret_cast<const uint4*>(gl));
        }

        // 3 products via ldmatrix fragments
        #pragma unroll
        for (int p = 0; p < 3; p++) {
            const uint32_t sa = sb32 + ((p == 2) ? SM_ALO : SM_AHI);
            const uint32_t sbb = sb32 + ((p == 1) ? SM_BLO : SM_BHI);
            uint32_t af0[4], af1[4];
            LDMX4(af0, sa + a_off0);
            LDMX4(af1, sa + a_off1);
            #pragma unroll
            for (int j2 = 0; j2 < 4; j2++) {
                uint32_t bf[4];
                LDMX4(bf, sbb + b_off + (uint32_t)(j2 * 16 * 24 * 2));
                mma_bf16(&acc[(0 * 8 + j2 * 2 + 0) * 4], af0, bf[0], bf[1]);
                mma_bf16(&acc[(1 * 8 + j2 * 2 + 0) * 4], af1, bf[0], bf[1]);
                mma_bf16(&acc[(0 * 8 + j2 * 2 + 1) * 4], af0, bf[2], bf[3]);
                mma_bf16(&acc[(1 * 8 + j2 * 2 + 1) * 4], af1, bf[2], bf[3]);
            }
        }
        __syncthreads();
    }

    // ---- write C tile to smem (stride 129 floats) ----
    #pragma unroll
    for (int mt = 0; mt < 2; mt++) {
        #pragma unroll
        for (int j = 0; j < 8; j++) {
            int r0  = rbase + mt * 16 + g;
            int col = cbase + j * 8 + tig * 2;
            const float* a4 = &acc[(mt * 8 + j) * 4];
            smf[SM_C / 4 + r0 * 129 + col]           = a4[0];
            smf[SM_C / 4 + r0 * 129 + col + 1]       = a4[1];
            smf[SM_C / 4 + (r0 + 8) * 129 + col]     = a4[2];
            smf[SM_C / 4 + (r0 + 8) * 129 + col + 1] = a4[3];
        }
    }
    __syncthreads();

    // ---- fused epilogue: half-rows, normalize + project ----
    {
        int half = tid >> 7;
        int row  = tid & 127;
        int cb   = half * 64;
        float ss = 0.f;
        float a20[NUM_CLS];
        #pragma unroll
        for (int k = 0; k < NUM_CLS; k++) a20[k] = 0.f;

        #pragma unroll 4
        for (int j = 0; j < 64; j++) {
            int col = cb + j;
            float h = smf[SM_C / 4 + row * 129 + col] + smf[SM_BIAS / 4 + col];
            ss += h * h;
            const float4* wr = reinterpret_cast<const float4*>(&smf[SM_WN / 4 + col * NUM_CLS]);
            float4 w0 = wr[0], w1 = wr[1], w2 = wr[2], w3 = wr[3], w4 = wr[4];
            a20[0]  += h * w0.x; a20[1]  += h * w0.y; a20[2]  += h * w0.z; a20[3]  += h * w0.w;
            a20[4]  += h * w1.x; a20[5]  += h * w1.y; a20[6]  += h * w1.z; a20[7]  += h * w1.w;
            a20[8]  += h * w2.x; a20[9]  += h * w2.y; a20[10] += h * w2.z; a20[11] += h * w2.w;
            a20[12] += h * w3.x; a20[13] += h * w3.y; a20[14] += h * w3.z; a20[15] += h * w3.w;
            a20[16] += h * w4.x; a20[17] += h * w4.y; a20[18] += h * w4.z; a20[19] += h * w4.w;
        }
        if (half == 1) {
            float* pp = &smf[SM_PART / 4 + row * 21];
            pp[0] = ss;
            #pragma unroll
            for (int k = 0; k < NUM_CLS; k++) pp[1 + k] = a20[k];
        }
        __syncthreads();
        if (half == 0) {
            const float* pp = &smf[SM_PART / 4 + row * 21];
            ss += pp[0];
            #pragma unroll
            for (int k = 0; k < NUM_CLS; k++) a20[k] += pp[1 + k];
            int grow = block_row + row;
            if (grow < N_NODES) {
                float inv = 1.f / fmaxf(sqrtf(ss), 1e-12f);
                float* op = out + (size_t)grow * NUM_CLS;
                #pragma unroll
                for (int q = 0; q < 5; q++) {
                    float4 o;
                    o.x = a20[q * 4 + 0] * inv; o.y = a20[q * 4 + 1] * inv;
                    o.z = a20[q * 4 + 2] * inv; o.w = a20[q * 4 + 3] * inv;
                    *reinterpret_cast<float4*>(op + q * 4) = o;
                }
            }
        }
    }
}

// ---------------- launch ----------------
extern "C" void kernel_launch(void* const* d_in, const int* in_sizes, int n_in,
                              void* d_out, int out_size) {
    const float* x   = (const float*)d_in[0];
    const int*   ei  = (const int*)d_in[1];     // int32 (JAX demotes int64)
    const float* Wl  = (const float*)d_in[2];
    const float* bl  = (const float*)d_in[3];
    const float* Wr  = (const float*)d_in[4];
    const float* Wc  = (const float*)d_in[5];
    float*       out = (float*)d_out;

    cudaFuncSetAttribute(gemm_mma_kernel, cudaFuncAttributeMaxDynamicSharedMemorySize,
                         GEMM_SMEM_BYTES);

    zero_kernel<<<2048, 256>>>();
    normw_kernel<<<1, 32>>>(Wc);
    prepB_kernel<<<128, 256>>>(Wl, Wr);
    {
        int warps = (N_EDGES + E_PER_WARP - 1) / E_PER_WARP;
        long long total_threads = (long long)warps * 32;
        int blocks = (int)((total_threads + 255) / 256);
        scatter_kernel<<<blocks, 256>>>(x, ei);
    }
    gemm_mma_kernel<<<(N_NODES + 127) / 128, 256, GEMM_SMEM_BYTES>>>(x, bl, out);
}

// round 11
// speedup vs baseline: 2.0875x; 1.0323x over previous
#include <cuda_runtime.h>
#include <cuda_bf16.h>
#include <cstdint>
#include <math.h>

#define N_NODES 100000
#define HID     128
#define NUM_CLS 20
#define N_EDGES 625000
#define E_PER_WARP 4

// ---------------- scratch (static device globals; no allocation) ----------------
__device__ float d_summed[N_NODES * HID];          // 51.2 MB
__device__ int   d_counts[N_NODES];
__device__ __nv_bfloat16 d_Bhi[128 * 256];         // weight^T bf16-hi  [n][k]
__device__ __nv_bfloat16 d_Blo[128 * 256];         // weight^T bf16-lo  [n][k]
__device__ float d_Wn[HID * NUM_CLS];              // col-normalized classifier weight

__device__ __forceinline__ uint32_t smem_u32(const void* p) {
    uint32_t a;
    asm("{ .reg .u64 t; cvta.to.shared.u64 t, %1; cvt.u32.u64 %0, t; }" : "=r"(a) : "l"(p));
    return a;
}

// ---------------- kernel 1: zero scratch ----------------
__global__ void zero_kernel() {
    int idx = blockIdx.x * blockDim.x + threadIdx.x;
    int stride = gridDim.x * blockDim.x;
    float4* s4 = reinterpret_cast<float4*>(d_summed);
    const int n4 = N_NODES * HID / 4;
    for (int i = idx; i < n4; i += stride) s4[i] = make_float4(0.f, 0.f, 0.f, 0.f);
    for (int i = idx; i < N_NODES; i += stride) d_counts[i] = 0;
}

// ---------------- kernel 2: column-normalize W_cls ----------------
__global__ void normw_kernel(const float* __restrict__ Wc) {
    int c = threadIdx.x;
    if (c >= NUM_CLS) return;
    float s = 0.f;
    for (int j = 0; j < HID; j++) {
        float v = Wc[j * NUM_CLS + c];
        s += v * v;
    }
    float inv = 1.f / fmaxf(sqrtf(s), 1e-12f);
    for (int j = 0; j < HID; j++)
        d_Wn[j * NUM_CLS + c] = Wc[j * NUM_CLS + c] * inv;
}

// ---------------- kernel 2b: B = [W_l;W_r]^T split into bf16 hi/lo ----------------
__global__ void prepB_kernel(const float* __restrict__ Wl, const float* __restrict__ Wr) {
    int n = blockIdx.x;    // 0..127 output col
    int k = threadIdx.x;   // 0..255
    float w = (k < 128) ? Wl[k * 128 + n] : Wr[(k - 128) * 128 + n];
    __nv_bfloat16 hi = __float2bfloat16_rn(w);
    __nv_bfloat16 lo = __float2bfloat16_rn(w - __bfloat162float(hi));
    d_Bhi[n * 256 + k] = hi;
    d_Blo[n * 256 + k] = lo;
}

// ---------------- kernel 3: edge scatter, 4 edges/warp (MLP=4, 32 regs) ----------------
__global__ void scatter_kernel(const float* __restrict__ x, const int* __restrict__ ei) {
    int gw   = (blockIdx.x * blockDim.x + threadIdx.x) >> 5;
    int lane = threadIdx.x & 31;
    int e0 = gw * E_PER_WARP;
    if (e0 >= N_EDGES) return;

    int src[E_PER_WARP], dst[E_PER_WARP];
    #pragma unroll
    for (int i = 0; i < E_PER_WARP; i++) {
        int e = e0 + i;
        if (e < N_EDGES) {
            src[i] = __ldg(&ei[e]);
            dst[i] = __ldg(&ei[N_EDGES + e]);
        } else {
            src[i] = -1;
        }
    }
    float4 v[E_PER_WARP];
    #pragma unroll
    for (int i = 0; i < E_PER_WARP; i++)
        if (src[i] >= 0)
            v[i] = __ldg(reinterpret_cast<const float4*>(x + (size_t)src[i] * HID) + lane);
    #pragma unroll
    for (int i = 0; i < E_PER_WARP; i++) {
        if (src[i] >= 0) {
            float* p = d_summed + (size_t)dst[i] * HID + lane * 4;
            asm volatile("red.global.add.v4.f32 [%0], {%1,%2,%3,%4};"
                         :: "l"(p), "f"(v[i].x), "f"(v[i].y), "f"(v[i].z), "f"(v[i].w)
                         : "memory");
            if (lane == 0) atomicAdd(&d_counts[dst[i]], 1);
        }
    }
}

// ---------------- kernel 4: mma.sync bf16-split GEMM, double-buffered ----------------
// smem byte offsets: two stage buffers of 24576 B each (AHI/ALO/BHI/BLO x 6144)
#define STAGE_BUF  24576
#define SM_AHI   0
#define SM_ALO   6144
#define SM_BHI   12288
#define SM_BLO   18432
#define SM_C     0          // reuses stage region after mainloop: 128*129*4 = 66048
#define SM_WN    66048      // 128*20*4 = 10240
#define SM_BIAS  76288      // 512
#define SM_INVC  76800      // 512
#define SM_PART  77312      // 128*21*4 = 10752 -> total 88064
#define GEMM_SMEM_BYTES 88064

__device__ __forceinline__ void mma_bf16(float* c, const uint32_t* a, uint32_t b0, uint32_t b1) {
    asm volatile("mma.sync.aligned.m16n8k16.row.col.f32.bf16.bf16.f32 "
                 "{%0,%1,%2,%3}, {%4,%5,%6,%7}, {%8,%9}, {%0,%1,%2,%3};"
                 : "+f"(c[0]), "+f"(c[1]), "+f"(c[2]), "+f"(c[3])
                 : "r"(a[0]), "r"(a[1]), "r"(a[2]), "r"(a[3]), "r"(b0), "r"(b1));
}
#define LDMX4(r, addr) \
    asm volatile("ldmatrix.sync.aligned.m8n8.x4.shared.b16 {%0,%1,%2,%3}, [%4];" \
                 : "=r"((r)[0]), "=r"((r)[1]), "=r"((r)[2]), "=r"((r)[3]) : "r"(addr))

__global__ __launch_bounds__(256, 2)
void gemm_mma_kernel(const float* __restrict__ x,
                     const float* __restrict__ bl,
                     float* __restrict__ out) {
    extern __shared__ char sm[];
    float* smf = reinterpret_cast<float*>(sm);
    const uint32_t sb32 = smem_u32(sm);
    const int tid  = threadIdx.x;
    const int wid  = tid >> 5;
    const int lane = tid & 31;
    const int g    = lane >> 2;
    const int tig  = lane & 3;
    const int warp_m = wid >> 1;
    const int warp_n = wid & 1;
    const int rbase = warp_m * 32;
    const int cbase = warp_n * 64;
    const int block_row = blockIdx.x * 128;

    // ldmatrix per-lane source coords
    const int lm_mat = lane >> 3;
    const int lm_rin = lane & 7;
    const uint32_t a_off0 = (uint32_t)(((rbase + lm_rin + (lm_mat & 1) * 8) * 24 + (lm_mat >> 1) * 8) * 2);
    const uint32_t a_off1 = a_off0 + 16 * 24 * 2;
    const uint32_t b_off  = (uint32_t)(((cbase + (lm_mat >> 1) * 8 + lm_rin) * 24 + (lm_mat & 1) * 8) * 2);

    // A staging coords (2 float4 per thread per chunk)
    const int a_row0 = tid >> 2;
    const int a_kq0  = tid & 3;
    const int a_row1 = (tid + 256) >> 2;
    const int a_kq1  = (tid + 256) & 3;
    // B staging coords
    const int b_row  = tid >> 1;
    const int b_half = tid & 1;

    // ---- init: Wn, bias, invc ----
    for (int i = tid; i < HID * NUM_CLS; i += 256) smf[SM_WN / 4 + i] = d_Wn[i];
    if (tid < 128) {
        smf[SM_BIAS / 4 + tid] = __ldg(&bl[tid]);
        int r = block_row + tid;
        int cnt = (r < N_NODES) ? d_counts[r] : 1;
        smf[SM_INVC / 4 + tid] = 1.f / (float)max(cnt, 1);
    }
    __syncthreads();
    const float ic0 = smf[SM_INVC / 4 + a_row0];
    const float ic1 = smf[SM_INVC / 4 + a_row1];

    float acc[64];
    #pragma unroll
    for (int i = 0; i < 64; i++) acc[i] = 0.f;

    const int grow0 = block_row + a_row0;
    const int grow1 = block_row + a_row1;

    // helper lambdas (inlined by compiler)
    auto load_chunk = [&](int c, float4& av0, float4& av1, uint4& vh, uint4& vl) {
        const int kb = c * 16;
        const bool left = (c < 8);
        av0 = make_float4(0.f, 0.f, 0.f, 0.f);
        av1 = make_float4(0.f, 0.f, 0.f, 0.f);
        if (grow0 < N_NODES) {
            const float* base = left ? &d_summed[(size_t)grow0 * HID + kb]
                                     : &x[(size_t)grow0 * HID + (kb - 128)];
            av0 = __ldg(reinterpret_cast<const float4*>(base + a_kq0 * 4));
        }
        if (grow1 < N_NODES) {
            const float* base = left ? &d_summed[(size_t)grow1 * HID + kb]
                                     : &x[(size_t)grow1 * HID + (kb - 128)];
            av1 = __ldg(reinterpret_cast<const float4*>(base + a_kq1 * 4));
        }
        const char* gh = reinterpret_cast<const char*>(d_Bhi) + b_row * 512 + kb * 2 + b_half * 16;
        const char* gl = reinterpret_cast<const char*>(d_Blo) + b_row * 512 + kb * 2 + b_half * 16;
        vh = __ldg(reinterpret_cast<const uint4*>(gh));
        vl = __ldg(reinterpret_cast<const uint4*>(gl));
    };
    auto store_chunk = [&](int c, const float4& av0, const float4& av1,
                           const uint4& vh, const uint4& vl) {
        char* buf = sm + (c & 1) * STAGE_BUF;
        const bool left = (c < 8);
        {
            float4 a = av0;
            if (left) { a.x *= ic0; a.y *= ic0; a.z *= ic0; a.w *= ic0; }
            __nv_bfloat162 h01, h23, l01, l23;
            h01.x = __float2bfloat16_rn(a.x); h01.y = __float2bfloat16_rn(a.y);
            h23.x = __float2bfloat16_rn(a.z); h23.y = __float2bfloat16_rn(a.w);
            l01.x = __float2bfloat16_rn(a.x - __bfloat162float(h01.x));
            l01.y = __float2bfloat16_rn(a.y - __bfloat162float(h01.y));
            l23.x = __float2bfloat16_rn(a.z - __bfloat162float(h23.x));
            l23.y = __float2bfloat16_rn(a.w - __bfloat162float(h23.y));
            uint32_t off = (uint32_t)(a_row0 * 24 + a_kq0 * 4) * 2;
            *reinterpret_cast<__nv_bfloat162*>(buf + SM_AHI + off)     = h01;
            *reinterpret_cast<__nv_bfloat162*>(buf + SM_AHI + off + 4) = h23;
            *reinterpret_cast<__nv_bfloat162*>(buf + SM_ALO + off)     = l01;
            *reinterpret_cast<__nv_bfloat162*>(buf + SM_ALO + off + 4) = l23;
        }
        {
            float4 a = av1;
            if (left) { a.x *= ic1; a.y *= ic1; a.z *= ic1; a.w *= ic1; }
            __nv_bfloat162 h01, h23, l01, l23;
            h01.x = __float2bfloat16_rn(a.x); h01.y = __float2bfloat16_rn(a.y);
            h23.x = __float2bfloat16_rn(a.z); h23.y = __float2bfloat16_rn(a.w);
            l01.x = __float2bfloat16_rn(a.x - __bfloat162float(h01.x));
            l01.y = __float2bfloat16_rn(a.y - __bfloat162float(h01.y));
            l23.x = __float2bfloat16_rn(a.z - __bfloat162float(h23.x));
            l23.y = __float2bfloat16_rn(a.w - __bfloat162float(h23.y));
            uint32_t off = (uint32_t)(a_row1 * 24 + a_kq1 * 4) * 2;
            *reinterpret_cast<__nv_bfloat162*>(buf + SM_AHI + off)     = h01;
            *reinterpret_cast<__nv_bfloat162*>(buf + SM_AHI + off + 4) = h23;
            *reinterpret_cast<__nv_bfloat162*>(buf + SM_ALO + off)     = l01;
            *reinterpret_cast<__nv_bfloat162*>(buf + SM_ALO + off + 4) = l23;
        }
        *reinterpret_cast<uint4*>(buf + SM_BHI + b_row * 48 + b_half * 16) = vh;
        *reinterpret_cast<uint4*>(buf + SM_BLO + b_row * 48 + b_half * 16) = vl;
    };

    // ---- prologue: stage chunk 0 into buffer 0 ----
    {
        float4 av0, av1; uint4 vh, vl;
        load_chunk(0, av0, av1, vh, vl);
        store_chunk(0, av0, av1, vh, vl);
    }
    __syncthreads();

    // ---- mainloop: one sync per chunk; MMA(c) overlaps loads/stores of c+1 ----
    for (int c = 0; c < 16; c++) {
        float4 av0, av1; uint4 vh, vl;
        if (c < 15) load_chunk(c + 1, av0, av1, vh, vl);

        const uint32_t bufb = sb32 + (uint32_t)((c & 1) * STAGE_BUF);
        #pragma unroll
        for (int p = 0; p < 3; p++) {
            const uint32_t sa  = bufb + ((p == 2) ? SM_ALO : SM_AHI);
            const uint32_t sbb = bufb + ((p == 1) ? SM_BLO : SM_BHI);
            uint32_t af0[4], af1[4];
            LDMX4(af0, sa + a_off0);
            LDMX4(af1, sa + a_off1);
            #pragma unroll
            for (int j2 = 0; j2 < 4; j2++) {
                uint32_t bf[4];
                LDMX4(bf, sbb + b_off + (uint32_t)(j2 * 16 * 24 * 2));
                mma_bf16(&acc[(0 * 8 + j2 * 2 + 0) * 4], af0, bf[0], bf[1]);
                mma_bf16(&acc[(1 * 8 + j2 * 2 + 0) * 4], af1, bf[0], bf[1]);
                mma_bf16(&acc[(0 * 8 + j2 * 2 + 1) * 4], af0, bf[2], bf[3]);
                mma_bf16(&acc[(1 * 8 + j2 * 2 + 1) * 4], af1, bf[2], bf[3]);
            }
        }
        if (c < 15) store_chunk(c + 1, av0, av1, vh, vl);
        __syncthreads();
    }

    // ---- write C tile to smem (stride 129 floats) ----
    #pragma unroll
    for (int mt = 0; mt < 2; mt++) {
        #pragma unroll
        for (int j = 0; j < 8; j++) {
            int r0  = rbase + mt * 16 + g;
            int col = cbase + j * 8 + tig * 2;
            const float* a4 = &acc[(mt * 8 + j) * 4];
            smf[SM_C / 4 + r0 * 129 + col]           = a4[0];
            smf[SM_C / 4 + r0 * 129 + col + 1]       = a4[1];
            smf[SM_C / 4 + (r0 + 8) * 129 + col]     = a4[2];
            smf[SM_C / 4 + (r0 + 8) * 129 + col + 1] = a4[3];
        }
    }
    __syncthreads();

    // ---- fused epilogue: half-rows, normalize + project ----
    {
        int half = tid >> 7;
        int row  = tid & 127;
        int cb   = half * 64;
        float ss = 0.f;
        float a20[NUM_CLS];
        #pragma unroll
        for (int k = 0; k < NUM_CLS; k++) a20[k] = 0.f;

        #pragma unroll 4
        for (int j = 0; j < 64; j++) {
            int col = cb + j;
            float h = smf[SM_C / 4 + row * 129 + col] + smf[SM_BIAS / 4 + col];
            ss += h * h;
            const float4* wr = reinterpret_cast<const float4*>(&smf[SM_WN / 4 + col * NUM_CLS]);
            float4 w0 = wr[0], w1 = wr[1], w2 = wr[2], w3 = wr[3], w4 = wr[4];
            a20[0]  += h * w0.x; a20[1]  += h * w0.y; a20[2]  += h * w0.z; a20[3]  += h * w0.w;
            a20[4]  += h * w1.x; a20[5]  += h * w1.y; a20[6]  += h * w1.z; a20[7]  += h * w1.w;
            a20[8]  += h * w2.x; a20[9]  += h * w2.y; a20[10] += h * w2.z; a20[11] += h * w2.w;
            a20[12] += h * w3.x; a20[13] += h * w3.y; a20[14] += h * w3.z; a20[15] += h * w3.w;
            a20[16] += h * w4.x; a20[17] += h * w4.y; a20[18] += h * w4.z; a20[19] += h * w4.w;
        }
        if (half == 1) {
            float* pp = &smf[SM_PART / 4 + row * 21];
            pp[0] = ss;
            #pragma unroll
            for (int k = 0; k < NUM_CLS; k++) pp[1 + k] = a20[k];
        }
        __syncthreads();
        if (half == 0) {
            const float* pp = &smf[SM_PART / 4 + row * 21];
            ss += pp[0];
            #pragma unroll
            for (int k = 0; k < NUM_CLS; k++) a20[k] += pp[1 + k];
            int grow = block_row + row;
            if (grow < N_NODES) {
                float inv = 1.f / fmaxf(sqrtf(ss), 1e-12f);
                float* op = out + (size_t)grow * NUM_CLS;
                #pragma unroll
                for (int q = 0; q < 5; q++) {
                    float4 o;
                    o.x = a20[q * 4 + 0] * inv; o.y = a20[q * 4 + 1] * inv;
                    o.z = a20[q * 4 + 2] * inv; o.w = a20[q * 4 + 3] * inv;
                    *reinterpret_cast<float4*>(op + q * 4) = o;
                }
            }
        }
    }
}

// ---------------- launch ----------------
extern "C" void kernel_launch(void* const* d_in, const int* in_sizes, int n_in,
                              void* d_out, int out_size) {
    const float* x   = (const float*)d_in[0];
    const int*   ei  = (const int*)d_in[1];     // int32 (JAX demotes int64)
    const float* Wl  = (const float*)d_in[2];
    const float* bl  = (const float*)d_in[3];
    const float* Wr  = (const float*)d_in[4];
    const float* Wc  = (const float*)d_in[5];
    float*       out = (float*)d_out;

    cudaFuncSetAttribute(gemm_mma_kernel, cudaFuncAttributeMaxDynamicSharedMemorySize,
                         GEMM_SMEM_BYTES);

    zero_kernel<<<2048, 256>>>();
    normw_kernel<<<1, 32>>>(Wc);
    prepB_kernel<<<128, 256>>>(Wl, Wr);
    {
        int warps = (N_EDGES + E_PER_WARP - 1) / E_PER_WARP;
        long long total_threads = (long long)warps * 32;
        int blocks = (int)((total_threads + 255) / 256);
        scatter_kernel<<<blocks, 256>>>(x, ei);
    }
    gemm_mma_kernel<<<(N_NODES + 127) / 128, 256, GEMM_SMEM_BYTES>>>(x, bl, out);
}

// round 12
// speedup vs baseline: 2.3138x; 1.1084x over previous
#include <cuda_runtime.h>
#include <cuda_bf16.h>
#include <cstdint>
#include <math.h>

#define N_NODES 100000
#define HID     128
#define NUM_CLS 20
#define N_EDGES 625000
#define SCAN_BS 256
#define SCAN_NB ((N_NODES + SCAN_BS - 1) / SCAN_BS)   // 391

// ---------------- scratch (static device globals; no allocation) ----------------
__device__ float d_summed[N_NODES * HID];          // holds aggr (mean) now
__device__ int   d_counts[N_NODES];
__device__ int   d_starts[N_NODES];
__device__ int   d_cursor[N_NODES];
__device__ int   d_bucket[N_EDGES];
__device__ int   d_bsum[512];
__device__ __nv_bfloat16 d_Bhi[128 * 256];         // weight^T bf16-hi  [n][k]
__device__ __nv_bfloat16 d_Blo[128 * 256];         // weight^T bf16-lo  [n][k]
__device__ float d_Wn[HID * NUM_CLS];              // col-normalized classifier weight

__device__ __forceinline__ uint32_t smem_u32(const void* p) {
    uint32_t a;
    asm("{ .reg .u64 t; cvta.to.shared.u64 t, %1; cvt.u32.u64 %0, t; }" : "=r"(a) : "l"(p));
    return a;
}

// ---------------- CSR build: histogram + scan + bucket fill ----------------
__global__ void zero_counts_kernel() {
    int i = blockIdx.x * blockDim.x + threadIdx.x;
    if (i < N_NODES) d_counts[i] = 0;
}

__global__ void hist_kernel(const int* __restrict__ ei) {
    int e = blockIdx.x * blockDim.x + threadIdx.x;
    if (e < N_EDGES) atomicAdd(&d_counts[__ldg(&ei[N_EDGES + e])], 1);
}

__global__ void scan1_kernel() {
    __shared__ int s[SCAN_BS];
    int i = blockIdx.x * SCAN_BS + threadIdx.x;
    int v = (i < N_NODES) ? d_counts[i] : 0;
    s[threadIdx.x] = v;
    __syncthreads();
    for (int off = 1; off < SCAN_BS; off <<= 1) {
        int t = (threadIdx.x >= off) ? s[threadIdx.x - off] : 0;
        __syncthreads();
        s[threadIdx.x] += t;
        __syncthreads();
    }
    if (i < N_NODES) d_starts[i] = s[threadIdx.x] - v;   // exclusive within block
    if (threadIdx.x == SCAN_BS - 1) d_bsum[blockIdx.x] = s[SCAN_BS - 1];
}

__global__ void scan2_kernel() {
    __shared__ int s[512];
    int t = threadIdx.x;
    int orig = (t < SCAN_NB) ? d_bsum[t] : 0;
    s[t] = orig;
    __syncthreads();
    for (int off = 1; off < 512; off <<= 1) {
        int v = (t >= off) ? s[t - off] : 0;
        __syncthreads();
        s[t] += v;
        __syncthreads();
    }
    if (t < SCAN_NB) d_bsum[t] = s[t] - orig;            // exclusive block offsets
}

__global__ void scan3_kernel() {
    int i = blockIdx.x * SCAN_BS + threadIdx.x;
    if (i < N_NODES) {
        int v = d_starts[i] + d_bsum[blockIdx.x];
        d_starts[i] = v;
        d_cursor[i] = v;
    }
}

__global__ void fill_kernel(const int* __restrict__ ei) {
    int e = blockIdx.x * blockDim.x + threadIdx.x;
    if (e < N_EDGES) {
        int dst = __ldg(&ei[N_EDGES + e]);
        int pos = atomicAdd(&d_cursor[dst], 1);
        d_bucket[pos] = __ldg(&ei[e]);
    }
}

// ---------------- aggregate: warp per node, pull-gather, plain stores ----------------
__global__ void agg_kernel(const float* __restrict__ x) {
    int gw   = (blockIdx.x * blockDim.x + threadIdx.x) >> 5;
    int lane = threadIdx.x & 31;
    if (gw >= N_NODES) return;
    int deg   = __ldg(&d_counts[gw]);
    int start = __ldg(&d_starts[gw]);

    float4 acc = make_float4(0.f, 0.f, 0.f, 0.f);
    int i = 0;
    for (; i + 4 <= deg; i += 4) {
        int s0 = __ldg(&d_bucket[start + i]);
        int s1 = __ldg(&d_bucket[start + i + 1]);
        int s2 = __ldg(&d_bucket[start + i + 2]);
        int s3 = __ldg(&d_bucket[start + i + 3]);
        float4 v0 = __ldg(reinterpret_cast<const float4*>(x + (size_t)s0 * HID) + lane);
        float4 v1 = __ldg(reinterpret_cast<const float4*>(x + (size_t)s1 * HID) + lane);
        float4 v2 = __ldg(reinterpret_cast<const float4*>(x + (size_t)s2 * HID) + lane);
        float4 v3 = __ldg(reinterpret_cast<const float4*>(x + (size_t)s3 * HID) + lane);
        acc.x += v0.x + v1.x + v2.x + v3.x;
        acc.y += v0.y + v1.y + v2.y + v3.y;
        acc.z += v0.z + v1.z + v2.z + v3.z;
        acc.w += v0.w + v1.w + v2.w + v3.w;
    }
    for (; i < deg; i++) {
        int s = __ldg(&d_bucket[start + i]);
        float4 v = __ldg(reinterpret_cast<const float4*>(x + (size_t)s * HID) + lane);
        acc.x += v.x; acc.y += v.y; acc.z += v.z; acc.w += v.w;
    }
    float inv = 1.f / (float)max(deg, 1);
    acc.x *= inv; acc.y *= inv; acc.z *= inv; acc.w *= inv;
    *reinterpret_cast<float4*>(&d_summed[(size_t)gw * HID + lane * 4]) = acc;
}

// ---------------- tiny prep kernels ----------------
__global__ void normw_kernel(const float* __restrict__ Wc) {
    int c = threadIdx.x;
    if (c >= NUM_CLS) return;
    float s = 0.f;
    for (int j = 0; j < HID; j++) {
        float v = Wc[j * NUM_CLS + c];
        s += v * v;
    }
    float inv = 1.f / fmaxf(sqrtf(s), 1e-12f);
    for (int j = 0; j < HID; j++)
        d_Wn[j * NUM_CLS + c] = Wc[j * NUM_CLS + c] * inv;
}

__global__ void prepB_kernel(const float* __restrict__ Wl, const float* __restrict__ Wr) {
    int n = blockIdx.x;
    int k = threadIdx.x;
    float w = (k < 128) ? Wl[k * 128 + n] : Wr[(k - 128) * 128 + n];
    __nv_bfloat16 hi = __float2bfloat16_rn(w);
    __nv_bfloat16 lo = __float2bfloat16_rn(w - __bfloat162float(hi));
    d_Bhi[n * 256 + k] = hi;
    d_Blo[n * 256 + k] = lo;
}

// ---------------- GEMM: mma.sync bf16-split, double-buffered, fused epilogue ----------
#define STAGE_BUF  24576
#define SM_AHI   0
#define SM_ALO   6144
#define SM_BHI   12288
#define SM_BLO   18432
#define SM_C     0          // reuses stage region after mainloop: 128*129*4 = 66048
#define SM_WN    66048
#define SM_BIAS  76288
#define SM_PART  77312      // 128*21*4 = 10752 -> total 88064
#define GEMM_SMEM_BYTES 88064

__device__ __forceinline__ void mma_bf16(float* c, const uint32_t* a, uint32_t b0, uint32_t b1) {
    asm volatile("mma.sync.aligned.m16n8k16.row.col.f32.bf16.bf16.f32 "
                 "{%0,%1,%2,%3}, {%4,%5,%6,%7}, {%8,%9}, {%0,%1,%2,%3};"
                 : "+f"(c[0]), "+f"(c[1]), "+f"(c[2]), "+f"(c[3])
                 : "r"(a[0]), "r"(a[1]), "r"(a[2]), "r"(a[3]), "r"(b0), "r"(b1));
}
#define LDMX4(r, addr) \
    asm volatile("ldmatrix.sync.aligned.m8n8.x4.shared.b16 {%0,%1,%2,%3}, [%4];" \
                 : "=r"((r)[0]), "=r"((r)[1]), "=r"((r)[2]), "=r"((r)[3]) : "r"(addr))

__global__ __launch_bounds__(256, 2)
void gemm_mma_kernel(const float* __restrict__ x,
                     const float* __restrict__ bl,
                     float* __restrict__ out) {
    extern __shared__ char sm[];
    float* smf = reinterpret_cast<float*>(sm);
    const uint32_t sb32 = smem_u32(sm);
    const int tid  = threadIdx.x;
    const int wid  = tid >> 5;
    const int lane = tid & 31;
    const int g    = lane >> 2;
    const int tig  = lane & 3;
    const int warp_m = wid >> 1;
    const int warp_n = wid & 1;
    const int rbase = warp_m * 32;
    const int cbase = warp_n * 64;
    const int block_row = blockIdx.x * 128;

    const int lm_mat = lane >> 3;
    const int lm_rin = lane & 7;
    const uint32_t a_off0 = (uint32_t)(((rbase + lm_rin + (lm_mat & 1) * 8) * 24 + (lm_mat >> 1) * 8) * 2);
    const uint32_t a_off1 = a_off0 + 16 * 24 * 2;
    const uint32_t b_off  = (uint32_t)(((cbase + (lm_mat >> 1) * 8 + lm_rin) * 24 + (lm_mat & 1) * 8) * 2);

    const int a_row0 = tid >> 2;
    const int a_kq0  = tid & 3;
    const int a_row1 = (tid + 256) >> 2;
    const int a_kq1  = (tid + 256) & 3;
    const int b_row  = tid >> 1;
    const int b_half = tid & 1;

    for (int i = tid; i < HID * NUM_CLS; i += 256) smf[SM_WN / 4 + i] = d_Wn[i];
    if (tid < 128) smf[SM_BIAS / 4 + tid] = __ldg(&bl[tid]);
    __syncthreads();

    float acc[64];
    #pragma unroll
    for (int i = 0; i < 64; i++) acc[i] = 0.f;

    const int grow0 = block_row + a_row0;
    const int grow1 = block_row + a_row1;

    auto load_chunk = [&](int c, float4& av0, float4& av1, uint4& vh, uint4& vl) {
        const int kb = c * 16;
        const bool left = (c < 8);
        av0 = make_float4(0.f, 0.f, 0.f, 0.f);
        av1 = make_float4(0.f, 0.f, 0.f, 0.f);
        if (grow0 < N_NODES) {
            const float* base = left ? &d_summed[(size_t)grow0 * HID + kb]
                                     : &x[(size_t)grow0 * HID + (kb - 128)];
            av0 = __ldg(reinterpret_cast<const float4*>(base + a_kq0 * 4));
        }
        if (grow1 < N_NODES) {
            const float* base = left ? &d_summed[(size_t)grow1 * HID + kb]
                                     : &x[(size_t)grow1 * HID + (kb - 128)];
            av1 = __ldg(reinterpret_cast<const float4*>(base + a_kq1 * 4));
        }
        const char* gh = reinterpret_cast<const char*>(d_Bhi) + b_row * 512 + kb * 2 + b_half * 16;
        const char* gl = reinterpret_cast<const char*>(d_Blo) + b_row * 512 + kb * 2 + b_half * 16;
        vh = __ldg(reinterpret_cast<const uint4*>(gh));
        vl = __ldg(reinterpret_cast<const uint4*>(gl));
    };
    auto store_chunk = [&](int c, const float4& av0, const float4& av1,
                           const uint4& vh, const uint4& vl) {
        char* buf = sm + (c & 1) * STAGE_BUF;
        {
            const float4& a = av0;
            __nv_bfloat162 h01, h23, l01, l23;
            h01.x = __float2bfloat16_rn(a.x); h01.y = __float2bfloat16_rn(a.y);
            h23.x = __float2bfloat16_rn(a.z); h23.y = __float2bfloat16_rn(a.w);
            l01.x = __float2bfloat16_rn(a.x - __bfloat162float(h01.x));
            l01.y = __float2bfloat16_rn(a.y - __bfloat162float(h01.y));
            l23.x = __float2bfloat16_rn(a.z - __bfloat162float(h23.x));
            l23.y = __float2bfloat16_rn(a.w - __bfloat162float(h23.y));
            uint32_t off = (uint32_t)(a_row0 * 24 + a_kq0 * 4) * 2;
            *reinterpret_cast<__nv_bfloat162*>(buf + SM_AHI + off)     = h01;
            *reinterpret_cast<__nv_bfloat162*>(buf + SM_AHI + off + 4) = h23;
            *reinterpret_cast<__nv_bfloat162*>(buf + SM_ALO + off)     = l01;
            *reinterpret_cast<__nv_bfloat162*>(buf + SM_ALO + off + 4) = l23;
        }
        {
            const float4& a = av1;
            __nv_bfloat162 h01, h23, l01, l23;
            h01.x = __float2bfloat16_rn(a.x); h01.y = __float2bfloat16_rn(a.y);
            h23.x = __float2bfloat16_rn(a.z); h23.y = __float2bfloat16_rn(a.w);
            l01.x = __float2bfloat16_rn(a.x - __bfloat162float(h01.x));
            l01.y = __float2bfloat16_rn(a.y - __bfloat162float(h01.y));
            l23.x = __float2bfloat16_rn(a.z - __bfloat162float(h23.x));
            l23.y = __float2bfloat16_rn(a.w - __bfloat162float(h23.y));
            uint32_t off = (uint32_t)(a_row1 * 24 + a_kq1 * 4) * 2;
            *reinterpret_cast<__nv_bfloat162*>(buf + SM_AHI + off)     = h01;
            *reinterpret_cast<__nv_bfloat162*>(buf + SM_AHI + off + 4) = h23;
            *reinterpret_cast<__nv_bfloat162*>(buf + SM_ALO + off)     = l01;
            *reinterpret_cast<__nv_bfloat162*>(buf + SM_ALO + off + 4) = l23;
        }
        *reinterpret_cast<uint4*>(buf + SM_BHI + b_row * 48 + b_half * 16) = vh;
        *reinterpret_cast<uint4*>(buf + SM_BLO + b_row * 48 + b_half * 16) = vl;
    };

    {
        float4 av0, av1; uint4 vh, vl;
        load_chunk(0, av0, av1, vh, vl);
        store_chunk(0, av0, av1, vh, vl);
    }
    __syncthreads();

    for (int c = 0; c < 16; c++) {
        float4 av0, av1; uint4 vh, vl;
        if (c < 15) load_chunk(c + 1, av0, av1, vh, vl);

        const uint32_t bufb = sb32 + (uint32_t)((c & 1) * STAGE_BUF);
        #pragma unroll
        for (int p = 0; p < 3; p++) {
            const uint32_t sa  = bufb + ((p == 2) ? SM_ALO : SM_AHI);
            const uint32_t sbb = bufb + ((p == 1) ? SM_BLO : SM_BHI);
            uint32_t af0[4], af1[4];
            LDMX4(af0, sa + a_off0);
            LDMX4(af1, sa + a_off1);
            #pragma unroll
            for (int j2 = 0; j2 < 4; j2++) {
                uint32_t bf[4];
                LDMX4(bf, sbb + b_off + (uint32_t)(j2 * 16 * 24 * 2));
                mma_bf16(&acc[(0 * 8 + j2 * 2 + 0) * 4], af0, bf[0], bf[1]);
                mma_bf16(&acc[(1 * 8 + j2 * 2 + 0) * 4], af1, bf[0], bf[1]);
                mma_bf16(&acc[(0 * 8 + j2 * 2 + 1) * 4], af0, bf[2], bf[3]);
                mma_bf16(&acc[(1 * 8 + j2 * 2 + 1) * 4], af1, bf[2], bf[3]);
            }
        }
        if (c < 15) store_chunk(c + 1, av0, av1, vh, vl);
        __syncthreads();
    }

    #pragma unroll
    for (int mt = 0; mt < 2; mt++) {
        #pragma unroll
        for (int j = 0; j < 8; j++) {
            int r0  = rbase + mt * 16 + g;
            int col = cbase + j * 8 + tig * 2;
            const float* a4 = &acc[(mt * 8 + j) * 4];
            smf[SM_C / 4 + r0 * 129 + col]           = a4[0];
            smf[SM_C / 4 + r0 * 129 + col + 1]       = a4[1];
            smf[SM_C / 4 + (r0 + 8) * 129 + col]     = a4[2];
            smf[SM_C / 4 + (r0 + 8) * 129 + col + 1] = a4[3];
        }
    }
    __syncthreads();

    {
        int half = tid >> 7;
        int row  = tid & 127;
        int cb   = half * 64;
        float ss = 0.f;
        float a20[NUM_CLS];
        #pragma unroll
        for (int k = 0; k < NUM_CLS; k++) a20[k] = 0.f;

        #pragma unroll 4
        for (int j = 0; j < 64; j++) {
            int col = cb + j;
            float h = smf[SM_C / 4 + row * 129 + col] + smf[SM_BIAS / 4 + col];
            ss += h * h;
            const float4* wr = reinterpret_cast<const float4*>(&smf[SM_WN / 4 + col * NUM_CLS]);
            float4 w0 = wr[0], w1 = wr[1], w2 = wr[2], w3 = wr[3], w4 = wr[4];
            a20[0]  += h * w0.x; a20[1]  += h * w0.y; a20[2]  += h * w0.z; a20[3]  += h * w0.w;
            a20[4]  += h * w1.x; a20[5]  += h * w1.y; a20[6]  += h * w1.z; a20[7]  += h * w1.w;
            a20[8]  += h * w2.x; a20[9]  += h * w2.y; a20[10] += h * w2.z; a20[11] += h * w2.w;
            a20[12] += h * w3.x; a20[13] += h * w3.y; a20[14] += h * w3.z; a20[15] += h * w3.w;
            a20[16] += h * w4.x; a20[17] += h * w4.y; a20[18] += h * w4.z; a20[19] += h * w4.w;
        }
        if (half == 1) {
            float* pp = &smf[SM_PART / 4 + row * 21];
            pp[0] = ss;
            #pragma unroll
            for (int k = 0; k < NUM_CLS; k++) pp[1 + k] = a20[k];
        }
        __syncthreads();
        if (half == 0) {
            const float* pp = &smf[SM_PART / 4 + row * 21];
            ss += pp[0];
            #pragma unroll
            for (int k = 0; k < NUM_CLS; k++) a20[k] += pp[1 + k];
            int grow = block_row + row;
            if (grow < N_NODES) {
                float inv = 1.f / fmaxf(sqrtf(ss), 1e-12f);
                float* op = out + (size_t)grow * NUM_CLS;
                #pragma unroll
                for (int q = 0; q < 5; q++) {
                    float4 o;
                    o.x = a20[q * 4 + 0] * inv; o.y = a20[q * 4 + 1] * inv;
                    o.z = a20[q * 4 + 2] * inv; o.w = a20[q * 4 + 3] * inv;
                    *reinterpret_cast<float4*>(op + q * 4) = o;
                }
            }
        }
    }
}

// ---------------- launch ----------------
extern "C" void kernel_launch(void* const* d_in, const int* in_sizes, int n_in,
                              void* d_out, int out_size) {
    const float* x   = (const float*)d_in[0];
    const int*   ei  = (const int*)d_in[1];     // int32 (JAX demotes int64)
    const float* Wl  = (const float*)d_in[2];
    const float* bl  = (const float*)d_in[3];
    const float* Wr  = (const float*)d_in[4];
    const float* Wc  = (const float*)d_in[5];
    float*       out = (float*)d_out;

    cudaFuncSetAttribute(gemm_mma_kernel, cudaFuncAttributeMaxDynamicSharedMemorySize,
                         GEMM_SMEM_BYTES);

    const int EB = (N_EDGES + 255) / 256;   // 2442
    zero_counts_kernel<<<SCAN_NB, SCAN_BS>>>();
    hist_kernel<<<EB, 256>>>(ei);
    scan1_kernel<<<SCAN_NB, SCAN_BS>>>();
    scan2_kernel<<<1, 512>>>();
    scan3_kernel<<<SCAN_NB, SCAN_BS>>>();
    fill_kernel<<<EB, 256>>>(ei);
    normw_kernel<<<1, 32>>>(Wc);
    prepB_kernel<<<128, 256>>>(Wl, Wr);
    agg_kernel<<<(N_NODES * 32 + 255) / 256, 256>>>(x);
    gemm_mma_kernel<<<(N_NODES + 127) / 128, 256, GEMM_SMEM_BYTES>>>(x, bl, out);
}